// round 12
// baseline (speedup 1.0000x reference)
#include <cuda_runtime.h>
#include <cuda_bf16.h>
#include <math.h>
#include <stdint.h>

#define BB 4
#define NN 2048
#define DIM 768
#define NH 12
#define HD 64
#define MROWS (BB*NN)   // 8192
#define SZT (BB*NH*NN*HD)

// q,k,v scratch as bf16 hi/lo pairs, [b,h,n,d] layout
__device__ __align__(16) __nv_bfloat16 g_qh[SZT], g_ql[SZT];
__device__ __align__(16) __nv_bfloat16 g_kh[SZT], g_kl[SZT];
__device__ __align__(16) __nv_bfloat16 g_vh[SZT], g_vl[SZT];
// pre-split inputs
__device__ __align__(16) __nv_bfloat16 g_xh[MROWS*DIM], g_xl[MROWS*DIM];
__device__ __align__(16) __nv_bfloat16 g_wqh[DIM*DIM], g_wql[DIM*DIM];
__device__ __align__(16) __nv_bfloat16 g_wkh[DIM*DIM], g_wkl[DIM*DIM];
__device__ __align__(16) __nv_bfloat16 g_wvh[DIM*DIM], g_wvl[DIM*DIM];

// ====================== helpers ======================
__device__ __forceinline__ uint32_t smem_u32(const void* p) {
    uint32_t a;
    asm("{ .reg .u64 t; cvta.to.shared.u64 t, %1; cvt.u32.u64 %0, t; }"
        : "=r"(a) : "l"(p));
    return a;
}
__device__ __forceinline__ void ldm_x4(uint32_t* r, uint32_t addr) {
    asm volatile("ldmatrix.sync.aligned.m8n8.x4.shared.b16 {%0,%1,%2,%3}, [%4];"
                 : "=r"(r[0]), "=r"(r[1]), "=r"(r[2]), "=r"(r[3]) : "r"(addr));
}
__device__ __forceinline__ void ldm_x4_t(uint32_t* r, uint32_t addr) {
    asm volatile("ldmatrix.sync.aligned.m8n8.x4.trans.shared.b16 {%0,%1,%2,%3}, [%4];"
                 : "=r"(r[0]), "=r"(r[1]), "=r"(r[2]), "=r"(r[3]) : "r"(addr));
}
__device__ __forceinline__ void mma_bf16(float* c, const uint32_t* a,
                                         uint32_t b0, uint32_t b1) {
    asm volatile(
        "mma.sync.aligned.m16n8k16.row.col.f32.bf16.bf16.f32 "
        "{%0,%1,%2,%3}, {%4,%5,%6,%7}, {%8,%9}, {%0,%1,%2,%3};"
        : "+f"(c[0]), "+f"(c[1]), "+f"(c[2]), "+f"(c[3])
        : "r"(a[0]), "r"(a[1]), "r"(a[2]), "r"(a[3]), "r"(b0), "r"(b1));
}
__device__ __forceinline__ uint32_t pk_lohi(float lo, float hi) {
    uint32_t r;
    asm("cvt.rn.bf16x2.f32 %0, %1, %2;" : "=r"(r) : "f"(hi), "f"(lo));
    return r;
}
__device__ __forceinline__ float ex2f(float x) {
    float y;
    asm("ex2.approx.ftz.f32 %0, %1;" : "=f"(y) : "f"(x));
    return y;
}
// Truncation split: hi = high 16 bits (packed via PRMT), lo = exact remainder (rn)
__device__ __forceinline__ void split2(float x0, float x1, uint32_t& h, uint32_t& l) {
    uint32_t u0 = __float_as_uint(x0), u1 = __float_as_uint(x1);
    h = __byte_perm(u0, u1, 0x7632);
    float h0 = __uint_as_float(u0 & 0xFFFF0000u);
    float h1 = __uint_as_float(u1 & 0xFFFF0000u);
    l = pk_lohi(x0 - h0, x1 - h1);
}
__device__ __forceinline__ void cpa16(uint32_t s, const void* g) {
    asm volatile("cp.async.cg.shared.global [%0], [%1], 16;"
                 :: "r"(s), "l"(g) : "memory");
}
#define CPA_COMMIT() asm volatile("cp.async.commit_group;" ::: "memory")
#define CPA_WAIT0()  asm volatile("cp.async.wait_group 0;" ::: "memory")

#define RPB 144
#define TILEB (128*RPB)           // 18432 B (128-row, 64-col tile)
#define KTILEB (64*RPB)           // 9216 B
#define KSTG (4*KTILEB)

// ===================== input splitting =====================
__global__ __launch_bounds__(256) void split_f32(
    const float4* __restrict__ src, uint2* __restrict__ dh,
    uint2* __restrict__ dl, int n4)
{
    int i = blockIdx.x * 256 + threadIdx.x;
    if (i >= n4) return;
    float4 v = src[i];
    uint32_t h0, l0, h1, l1;
    split2(v.x, v.y, h0, l0);
    split2(v.z, v.w, h1, l1);
    dh[i] = make_uint2(h0, h1);
    dl[i] = make_uint2(l0, l1);
}

// ===================== QKV GEMM: cp.async pipelined, pre-split bf16 =====================
#define QCH 32
#define QROWB 80                  // 32 bf16 = 64 B + 16 pad (conflict-free)
#define QTILE (128*QROWB)         // 10240 B
#define QSTG (4*QTILE)            // 40960 B per stage

__global__ __launch_bounds__(256, 2) void qkv_mma(
    const float* __restrict__ bq, const float* __restrict__ bk,
    const float* __restrict__ bv)
{
    extern __shared__ char smem[];
    const uint32_t sbase = smem_u32(smem);

    const int mat = blockIdx.z;
    const __nv_bfloat16* wh = (mat == 0) ? g_wqh : (mat == 1) ? g_wkh : g_wvh;
    const __nv_bfloat16* wl = (mat == 0) ? g_wql : (mat == 1) ? g_wkl : g_wvl;
    const float* bias = (mat == 0) ? bq : (mat == 1) ? bk : bv;
    __nv_bfloat16* dh = (mat == 0) ? g_qh : (mat == 1) ? g_kh : g_vh;
    __nv_bfloat16* dl = (mat == 0) ? g_ql : (mat == 1) ? g_kl : g_vl;
    const float osc = (mat == 0) ? 0.125f * 1.44269504f : 1.0f;  // fold softmax scale into Q

    const int m0 = blockIdx.y * 128;
    const int o0 = blockIdx.x * 128;
    const int tid = threadIdx.x;
    const int wid = tid >> 5, lane = tid & 31;
    const int warpM = wid & 3, warpN = wid >> 2;
    const int m0w = warpM * 32, n0w = warpN * 64;
    const uint32_t lm_off = (uint32_t)(lane & 15) * QROWB + (uint32_t)(lane >> 4) * 16;
    const int lrow = tid >> 2, lseg = tid & 3;

    float acc[2][8][4];
#pragma unroll
    for (int mt = 0; mt < 2; mt++)
#pragma unroll
        for (int nt = 0; nt < 8; nt++)
#pragma unroll
            for (int q = 0; q < 4; q++) acc[mt][nt][q] = 0.f;

    const int NC = DIM / QCH;   // 24 chunks

    // issue chunk 0
    {
        const uint32_t ss = sbase;
#pragma unroll
        for (int p = 0; p < 8; ++p) {
            int arr = p >> 1;
            int row = (p & 1) * 64 + lrow;
            const __nv_bfloat16* g =
                (arr == 0) ? g_xh + (size_t)(m0 + row) * DIM :
                (arr == 1) ? g_xl + (size_t)(m0 + row) * DIM :
                (arr == 2) ? wh + (size_t)(o0 + row) * DIM :
                             wl + (size_t)(o0 + row) * DIM;
            cpa16(ss + (uint32_t)(arr * QTILE + row * QROWB + lseg * 16),
                  g + lseg * 8);
        }
        CPA_COMMIT();
    }

    for (int c = 0; c < NC; ++c) {
        const int st = c & 1;
        CPA_WAIT0();
        __syncthreads();

        if (c + 1 < NC) {
            const int kb = (c + 1) * QCH;
            const uint32_t ss = sbase + (uint32_t)((st ^ 1) * QSTG);
#pragma unroll
            for (int p = 0; p < 8; ++p) {
                int arr = p >> 1;
                int row = (p & 1) * 64 + lrow;
                const __nv_bfloat16* g =
                    (arr == 0) ? g_xh + (size_t)(m0 + row) * DIM :
                    (arr == 1) ? g_xl + (size_t)(m0 + row) * DIM :
                    (arr == 2) ? wh + (size_t)(o0 + row) * DIM :
                                 wl + (size_t)(o0 + row) * DIM;
                cpa16(ss + (uint32_t)(arr * QTILE + row * QROWB + lseg * 16),
                      g + kb + lseg * 8);
            }
            CPA_COMMIT();
        }

        const uint32_t sAh = sbase + (uint32_t)(st * QSTG);
        const uint32_t sAl = sAh + QTILE;
        const uint32_t sBh = sAl + QTILE;
        const uint32_t sBl = sBh + QTILE;

#pragma unroll
        for (int ks = 0; ks < 2; ++ks) {
            const uint32_t kso = (uint32_t)ks * 32;
            uint32_t a_hi[2][4], a_lo[2][4];
#pragma unroll
            for (int mt = 0; mt < 2; mt++) {
                uint32_t base = (uint32_t)(m0w + 16 * mt) * QROWB + kso + lm_off;
                ldm_x4(a_hi[mt], sAh + base);
                ldm_x4(a_lo[mt], sAl + base);
            }
#pragma unroll
            for (int bp = 0; bp < 4; bp++) {
                uint32_t base = (uint32_t)(n0w + 16 * bp) * QROWB + kso + lm_off;
                uint32_t b_hi[4], b_lo[4];
                ldm_x4(b_hi, sBh + base);
                ldm_x4(b_lo, sBl + base);
#pragma unroll
                for (int half = 0; half < 2; half++) {
                    int nt = 2 * bp + half;
#pragma unroll
                    for (int mt = 0; mt < 2; mt++) {
                        mma_bf16(acc[mt][nt], a_hi[mt], b_hi[half], b_hi[half + 2]);
                        mma_bf16(acc[mt][nt], a_hi[mt], b_lo[half], b_lo[half + 2]);
                        mma_bf16(acc[mt][nt], a_lo[mt], b_hi[half], b_hi[half + 2]);
                    }
                }
            }
        }
    }

    // Epilogue: bias, optional Q scale, trunc-split, head-split store
#pragma unroll
    for (int mt = 0; mt < 2; mt++) {
#pragma unroll
        for (int nt = 0; nt < 8; nt++) {
            int row0 = m0 + m0w + 16 * mt + (lane >> 2);
            int col  = o0 + n0w + 8 * nt + 2 * (lane & 3);
            int h = col / HD, d = col & (HD - 1);
            float b0 = bias[col], b1 = bias[col + 1];
            {
                int b_ = row0 >> 11, n = row0 & (NN - 1);
                size_t idx = (((size_t)b_ * NH + h) * NN + n) * HD + d;
                uint32_t hh, ll;
                split2((acc[mt][nt][0] + b0) * osc, (acc[mt][nt][1] + b1) * osc, hh, ll);
                *(uint32_t*)(dh + idx) = hh;
                *(uint32_t*)(dl + idx) = ll;
            }
            {
                int row1 = row0 + 8;
                int b_ = row1 >> 11, n = row1 & (NN - 1);
                size_t idx = (((size_t)b_ * NH + h) * NN + n) * HD + d;
                uint32_t hh, ll;
                split2((acc[mt][nt][2] + b0) * osc, (acc[mt][nt][3] + b1) * osc, hh, ll);
                *(uint32_t*)(dh + idx) = hh;
                *(uint32_t*)(dl + idx) = ll;
            }
        }
    }
}

// ===================== Flash attention: cp.async double-buffered =====================
__global__ __launch_bounds__(256, 2) void attn_mma(float* __restrict__ out)
{
    extern __shared__ char smem[];
    const uint32_t sbase = smem_u32(smem);
    const uint32_t sQhi = sbase;
    const uint32_t sQlo = sbase + TILEB;
    const uint32_t sKV0 = sbase + 2 * TILEB;

    const int b = blockIdx.z, h = blockIdx.y;
    const int q0 = blockIdx.x * 128;
    const size_t hb = ((size_t)b * NH + h) * NN;
    const __nv_bfloat16* qh = g_qh + hb * HD;
    const __nv_bfloat16* ql = g_ql + hb * HD;
    const __nv_bfloat16* kh = g_kh + hb * HD;
    const __nv_bfloat16* kl = g_kl + hb * HD;
    const __nv_bfloat16* vh = g_vh + hb * HD;
    const __nv_bfloat16* vl = g_vl + hb * HD;

    const int tid = threadIdx.x;
    const int wid = tid >> 5, lane = tid & 31;
    const uint32_t lm_off = (uint32_t)(lane & 15) * RPB + (uint32_t)(lane >> 4) * 16;
    const int seg = tid & 7;
    const int rbase = tid >> 3;

    // issue tile 0, then copy Q (already scaled by qkv epilogue)
    {
#pragma unroll
        for (int p = 0; p < 8; ++p) {
            const int arr = p >> 1;
            int r = (p & 1) * 32 + rbase;
            const __nv_bfloat16* g = (arr == 0) ? kh : (arr == 1) ? kl
                                   : (arr == 2) ? vh : vl;
            cpa16(sKV0 + (uint32_t)(arr * KTILEB + r * RPB + seg * 16),
                  g + (size_t)r * HD + seg * 8);
        }
        CPA_COMMIT();
    }
#pragma unroll
    for (int p = 0; p < 8; ++p) {
        const int arr = p >> 2;
        int r = (p & 3) * 32 + rbase;
        const __nv_bfloat16* g = arr ? ql : qh;
        uint4 v = *(const uint4*)(g + (size_t)(q0 + r) * HD + seg * 8);
        *(uint4*)(smem + (arr ? TILEB : 0) + r * RPB + seg * 16) = v;
    }

    float o_[8][4];
    float mA = -INFINITY, mB = -INFINITY, lA = 0.f, lB = 0.f;
#pragma unroll
    for (int nt = 0; nt < 8; nt++)
#pragma unroll
        for (int q = 0; q < 4; q++) o_[nt][q] = 0.f;

    const int NT = NN / 64;
    for (int it = 0; it < NT; ++it) {
        const int st = it & 1;
        CPA_WAIT0();
        __syncthreads();

        if (it + 1 < NT) {
            const int j1 = (it + 1) * 64;
            const uint32_t sst = sKV0 + (uint32_t)(((it + 1) & 1) * KSTG);
#pragma unroll
            for (int p = 0; p < 8; ++p) {
                const int arr = p >> 1;
                int r = (p & 1) * 32 + rbase;
                const __nv_bfloat16* g = (arr == 0) ? kh : (arr == 1) ? kl
                                       : (arr == 2) ? vh : vl;
                cpa16(sst + (uint32_t)(arr * KTILEB + r * RPB + seg * 16),
                      g + (size_t)(j1 + r) * HD + seg * 8);
            }
            CPA_COMMIT();
        }

        const uint32_t sKhi = sKV0 + (uint32_t)(st * KSTG);
        const uint32_t sKlo = sKhi + KTILEB;
        const uint32_t sVhi = sKlo + KTILEB;
        const uint32_t sVlo = sVhi + KTILEB;

        // ---- S = Q @ K^T (log2-domain; Q pre-scaled) ----
        float s_[8][4];
#pragma unroll
        for (int nt = 0; nt < 8; nt++)
#pragma unroll
            for (int q = 0; q < 4; q++) s_[nt][q] = 0.f;

#pragma unroll
        for (int ks = 0; ks < 4; ++ks) {
            const uint32_t kso = (uint32_t)ks * 32;
            uint32_t ah[4], al[4];
            uint32_t ab = (uint32_t)(wid * 16) * RPB + kso + lm_off;
            ldm_x4(ah, sQhi + ab);
            ldm_x4(al, sQlo + ab);
#pragma unroll
            for (int bp = 0; bp < 4; bp++) {
                uint32_t bb = (uint32_t)(16 * bp) * RPB + kso + lm_off;
                uint32_t bh[4], bl[4];
                ldm_x4(bh, sKhi + bb);
                ldm_x4(bl, sKlo + bb);
#pragma unroll
                for (int half = 0; half < 2; half++) {
                    int nt = 2 * bp + half;
                    mma_bf16(s_[nt], ah, bh[half], bh[half + 2]);
                    mma_bf16(s_[nt], ah, bl[half], bl[half + 2]);
                    mma_bf16(s_[nt], al, bh[half], bh[half + 2]);
                }
            }
        }

        // ---- online softmax ----
        float mlA = -INFINITY, mlB = -INFINITY;
#pragma unroll
        for (int nt = 0; nt < 8; nt++) {
            mlA = fmaxf(mlA, fmaxf(s_[nt][0], s_[nt][1]));
            mlB = fmaxf(mlB, fmaxf(s_[nt][2], s_[nt][3]));
        }
#pragma unroll
        for (int off = 1; off <= 2; off <<= 1) {
            mlA = fmaxf(mlA, __shfl_xor_sync(0xffffffffu, mlA, off));
            mlB = fmaxf(mlB, __shfl_xor_sync(0xffffffffu, mlB, off));
        }
        float mnA = fmaxf(mA, mlA), mnB = fmaxf(mB, mlB);
        float aAl = ex2f(mA - mnA), aBl = ex2f(mB - mnB);
        mA = mnA; mB = mnB;
        float sumA = 0.f, sumB = 0.f;
#pragma unroll
        for (int nt = 0; nt < 8; nt++) {
            s_[nt][0] = ex2f(s_[nt][0] - mA);
            s_[nt][1] = ex2f(s_[nt][1] - mA);
            s_[nt][2] = ex2f(s_[nt][2] - mB);
            s_[nt][3] = ex2f(s_[nt][3] - mB);
            sumA += s_[nt][0] + s_[nt][1];
            sumB += s_[nt][2] + s_[nt][3];
            o_[nt][0] *= aAl; o_[nt][1] *= aAl;
            o_[nt][2] *= aBl; o_[nt][3] *= aBl;
        }
#pragma unroll
        for (int off = 1; off <= 2; off <<= 1) {
            sumA += __shfl_xor_sync(0xffffffffu, sumA, off);
            sumB += __shfl_xor_sync(0xffffffffu, sumB, off);
        }
        lA = lA * aAl + sumA;
        lB = lB * aBl + sumB;

        // ---- O += P @ V ----
#pragma unroll
        for (int t = 0; t < 4; t++) {
            uint32_t pah[4], pal[4];
#pragma unroll
            for (int i = 0; i < 4; i++) {
                const float* src = (i < 2) ? s_[2 * t] : s_[2 * t + 1];
                float x0 = src[(i & 1) ? 2 : 0];
                float x1 = src[(i & 1) ? 3 : 1];
                split2(x0, x1, pah[i], pal[i]);
            }
#pragma unroll
            for (int db = 0; db < 4; db++) {
                uint32_t vb = (uint32_t)(16 * t + (lane & 7) + ((lane >> 3) & 1) * 8) * RPB
                            + (uint32_t)(32 * db) + (uint32_t)(lane >> 4) * 16;
                uint32_t vhf[4], vlf[4];
                ldm_x4_t(vhf, sVhi + vb);
                ldm_x4_t(vlf, sVlo + vb);
#pragma unroll
                for (int half = 0; half < 2; half++) {
                    int nt = 2 * db + half;
                    mma_bf16(o_[nt], pah, vhf[2 * half], vhf[2 * half + 1]);
                    mma_bf16(o_[nt], pah, vlf[2 * half], vlf[2 * half + 1]);
                    mma_bf16(o_[nt], pal, vhf[2 * half], vhf[2 * half + 1]);
                }
            }
        }
    }

    // ---- epilogue ----
    const int rowA = q0 + 16 * wid + (lane >> 2);
    const int rowB = rowA + 8;
    const float invA = 1.f / lA, invB = 1.f / lB;
#pragma unroll
    for (int nt = 0; nt < 8; nt++) {
        int d0 = 8 * nt + 2 * (lane & 3);
        float2 vA = make_float2(o_[nt][0] * invA, o_[nt][1] * invA);
        float2 vB = make_float2(o_[nt][2] * invB, o_[nt][3] * invB);
        *(float2*)&out[((size_t)b * NN + rowA) * DIM + h * HD + d0] = vA;
        *(float2*)&out[((size_t)b * NN + rowB) * DIM + h * HD + d0] = vB;
    }
}

extern "C" void kernel_launch(void* const* d_in, const int* in_sizes, int n_in,
                              void* d_out, int out_size)
{
    (void)in_sizes; (void)n_in; (void)out_size;
    const float* x  = (const float*)d_in[0];
    const float* wq = (const float*)d_in[1];
    const float* bq = (const float*)d_in[2];
    const float* wk = (const float*)d_in[3];
    const float* bk = (const float*)d_in[4];
    const float* wv = (const float*)d_in[5];
    const float* bv = (const float*)d_in[6];
    float* out = (float*)d_out;

    // 1. split inputs to bf16 hi/lo (one pass each)
    {
        int n4x = MROWS * DIM / 4;
        __nv_bfloat16 *xh, *xl, *wqh, *wql, *wkh, *wkl, *wvh, *wvl;
        cudaGetSymbolAddress((void**)&xh, g_xh);
        cudaGetSymbolAddress((void**)&xl, g_xl);
        cudaGetSymbolAddress((void**)&wqh, g_wqh);
        cudaGetSymbolAddress((void**)&wql, g_wql);
        cudaGetSymbolAddress((void**)&wkh, g_wkh);
        cudaGetSymbolAddress((void**)&wkl, g_wkl);
        cudaGetSymbolAddress((void**)&wvh, g_wvh);
        cudaGetSymbolAddress((void**)&wvl, g_wvl);
        split_f32<<<(n4x + 255) / 256, 256>>>((const float4*)x, (uint2*)xh, (uint2*)xl, n4x);
        int n4w = DIM * DIM / 4;
        split_f32<<<(n4w + 255) / 256, 256>>>((const float4*)wq, (uint2*)wqh, (uint2*)wql, n4w);
        split_f32<<<(n4w + 255) / 256, 256>>>((const float4*)wk, (uint2*)wkh, (uint2*)wkl, n4w);
        split_f32<<<(n4w + 255) / 256, 256>>>((const float4*)wv, (uint2*)wvh, (uint2*)wvl, n4w);
    }

    // 2. QKV projections (pipelined bf16 GEMM)
    size_t q_smem = 2 * (size_t)QSTG;   // 81920 B
    cudaFuncSetAttribute(qkv_mma, cudaFuncAttributeMaxDynamicSharedMemorySize,
                         (int)q_smem);
    dim3 g1(DIM / 128, MROWS / 128, 3);
    qkv_mma<<<g1, 256, q_smem>>>(bq, bk, bv);

    // 3. attention
    size_t a_smem = 2 * (size_t)TILEB + 2 * (size_t)KSTG;   // 110592 B
    cudaFuncSetAttribute(attn_mma, cudaFuncAttributeMaxDynamicSharedMemorySize,
                         (int)a_smem);
    dim3 g2(NN / 128, NH, BB);
    attn_mma<<<g2, 256, a_smem>>>(out);
}

// round 13
// speedup vs baseline: 1.0004x; 1.0004x over previous
#include <cuda_runtime.h>
#include <cuda_bf16.h>
#include <math.h>
#include <stdint.h>

#define BB 4
#define NN 2048
#define DIM 768
#define NH 12
#define HD 64
#define MROWS (BB*NN)   // 8192
#define SZT (BB*NH*NN*HD)

// q,k,v scratch as bf16 hi/lo pairs, [b,h,n,d] layout
__device__ __align__(16) __nv_bfloat16 g_qh[SZT], g_ql[SZT];
__device__ __align__(16) __nv_bfloat16 g_kh[SZT], g_kl[SZT];
__device__ __align__(16) __nv_bfloat16 g_vh[SZT], g_vl[SZT];
// pre-split inputs
__device__ __align__(16) __nv_bfloat16 g_xh[MROWS*DIM], g_xl[MROWS*DIM];
__device__ __align__(16) __nv_bfloat16 g_wqh[DIM*DIM], g_wql[DIM*DIM];
__device__ __align__(16) __nv_bfloat16 g_wkh[DIM*DIM], g_wkl[DIM*DIM];
__device__ __align__(16) __nv_bfloat16 g_wvh[DIM*DIM], g_wvl[DIM*DIM];

// ====================== helpers ======================
__device__ __forceinline__ uint32_t smem_u32(const void* p) {
    uint32_t a;
    asm("{ .reg .u64 t; cvta.to.shared.u64 t, %1; cvt.u32.u64 %0, t; }"
        : "=r"(a) : "l"(p));
    return a;
}
__device__ __forceinline__ void ldm_x4(uint32_t* r, uint32_t addr) {
    asm volatile("ldmatrix.sync.aligned.m8n8.x4.shared.b16 {%0,%1,%2,%3}, [%4];"
                 : "=r"(r[0]), "=r"(r[1]), "=r"(r[2]), "=r"(r[3]) : "r"(addr));
}
__device__ __forceinline__ void ldm_x4_t(uint32_t* r, uint32_t addr) {
    asm volatile("ldmatrix.sync.aligned.m8n8.x4.trans.shared.b16 {%0,%1,%2,%3}, [%4];"
                 : "=r"(r[0]), "=r"(r[1]), "=r"(r[2]), "=r"(r[3]) : "r"(addr));
}
__device__ __forceinline__ void mma_bf16(float* c, const uint32_t* a,
                                         uint32_t b0, uint32_t b1) {
    asm volatile(
        "mma.sync.aligned.m16n8k16.row.col.f32.bf16.bf16.f32 "
        "{%0,%1,%2,%3}, {%4,%5,%6,%7}, {%8,%9}, {%0,%1,%2,%3};"
        : "+f"(c[0]), "+f"(c[1]), "+f"(c[2]), "+f"(c[3])
        : "r"(a[0]), "r"(a[1]), "r"(a[2]), "r"(a[3]), "r"(b0), "r"(b1));
}
__device__ __forceinline__ uint32_t pk_lohi(float lo, float hi) {
    uint32_t r;
    asm("cvt.rn.bf16x2.f32 %0, %1, %2;" : "=r"(r) : "f"(hi), "f"(lo));
    return r;
}
__device__ __forceinline__ float ex2f(float x) {
    float y;
    asm("ex2.approx.ftz.f32 %0, %1;" : "=f"(y) : "f"(x));
    return y;
}
// Truncation split: hi = high 16 bits (packed via PRMT), lo = exact remainder (rn)
__device__ __forceinline__ void split2(float x0, float x1, uint32_t& h, uint32_t& l) {
    uint32_t u0 = __float_as_uint(x0), u1 = __float_as_uint(x1);
    h = __byte_perm(u0, u1, 0x7632);
    float h0 = __uint_as_float(u0 & 0xFFFF0000u);
    float h1 = __uint_as_float(u1 & 0xFFFF0000u);
    l = pk_lohi(x0 - h0, x1 - h1);
}
__device__ __forceinline__ void cpa16(uint32_t s, const void* g) {
    asm volatile("cp.async.cg.shared.global [%0], [%1], 16;"
                 :: "r"(s), "l"(g) : "memory");
}
#define CPA_COMMIT() asm volatile("cp.async.commit_group;" ::: "memory")
#define CPA_WAIT0()  asm volatile("cp.async.wait_group 0;" ::: "memory")

#define RPB 144
#define TILEB (128*RPB)           // 18432 B
#define KTILEB (64*RPB)           // 9216 B
#define KSTG (4*KTILEB)

// ===================== input splitting =====================
__global__ __launch_bounds__(256) void split_f32(
    const float4* __restrict__ src, uint2* __restrict__ dh,
    uint2* __restrict__ dl, int n4)
{
    int i = blockIdx.x * 256 + threadIdx.x;
    if (i >= n4) return;
    float4 v = src[i];
    uint32_t h0, l0, h1, l1;
    split2(v.x, v.y, h0, l0);
    split2(v.z, v.w, h1, l1);
    dh[i] = make_uint2(h0, h1);
    dl[i] = make_uint2(l0, l1);
}

// ===================== QKV GEMM: cp.async pipelined, pre-split bf16 =====================
#define QCH 32
#define QROWB 80
#define QTILE (128*QROWB)         // 10240 B
#define QSTG (4*QTILE)            // 40960 B per stage

__global__ __launch_bounds__(256, 2) void qkv_mma(
    const float* __restrict__ bq, const float* __restrict__ bk,
    const float* __restrict__ bv)
{
    extern __shared__ char smem[];
    const uint32_t sbase = smem_u32(smem);

    const int mat = blockIdx.z;
    const __nv_bfloat16* wh = (mat == 0) ? g_wqh : (mat == 1) ? g_wkh : g_wvh;
    const __nv_bfloat16* wl = (mat == 0) ? g_wql : (mat == 1) ? g_wkl : g_wvl;
    const float* bias = (mat == 0) ? bq : (mat == 1) ? bk : bv;
    __nv_bfloat16* dh = (mat == 0) ? g_qh : (mat == 1) ? g_kh : g_vh;
    __nv_bfloat16* dl = (mat == 0) ? g_ql : (mat == 1) ? g_kl : g_vl;
    const float osc = (mat == 0) ? 0.125f * 1.44269504f : 1.0f;

    const int m0 = blockIdx.y * 128;
    const int o0 = blockIdx.x * 128;
    const int tid = threadIdx.x;
    const int wid = tid >> 5, lane = tid & 31;
    const int warpM = wid & 3, warpN = wid >> 2;
    const int m0w = warpM * 32, n0w = warpN * 64;
    const uint32_t lm_off = (uint32_t)(lane & 15) * QROWB + (uint32_t)(lane >> 4) * 16;
    const int lrow = tid >> 2, lseg = tid & 3;

    float acc[2][8][4];
#pragma unroll
    for (int mt = 0; mt < 2; mt++)
#pragma unroll
        for (int nt = 0; nt < 8; nt++)
#pragma unroll
            for (int q = 0; q < 4; q++) acc[mt][nt][q] = 0.f;

    const int NC = DIM / QCH;   // 24 chunks

    {
        const uint32_t ss = sbase;
#pragma unroll
        for (int p = 0; p < 8; ++p) {
            int arr = p >> 1;
            int row = (p & 1) * 64 + lrow;
            const __nv_bfloat16* g =
                (arr == 0) ? g_xh + (size_t)(m0 + row) * DIM :
                (arr == 1) ? g_xl + (size_t)(m0 + row) * DIM :
                (arr == 2) ? wh + (size_t)(o0 + row) * DIM :
                             wl + (size_t)(o0 + row) * DIM;
            cpa16(ss + (uint32_t)(arr * QTILE + row * QROWB + lseg * 16),
                  g + lseg * 8);
        }
        CPA_COMMIT();
    }

    for (int c = 0; c < NC; ++c) {
        const int st = c & 1;
        CPA_WAIT0();
        __syncthreads();

        if (c + 1 < NC) {
            const int kb = (c + 1) * QCH;
            const uint32_t ss = sbase + (uint32_t)((st ^ 1) * QSTG);
#pragma unroll
            for (int p = 0; p < 8; ++p) {
                int arr = p >> 1;
                int row = (p & 1) * 64 + lrow;
                const __nv_bfloat16* g =
                    (arr == 0) ? g_xh + (size_t)(m0 + row) * DIM :
                    (arr == 1) ? g_xl + (size_t)(m0 + row) * DIM :
                    (arr == 2) ? wh + (size_t)(o0 + row) * DIM :
                                 wl + (size_t)(o0 + row) * DIM;
                cpa16(ss + (uint32_t)(arr * QTILE + row * QROWB + lseg * 16),
                      g + kb + lseg * 8);
            }
            CPA_COMMIT();
        }

        const uint32_t sAh = sbase + (uint32_t)(st * QSTG);
        const uint32_t sAl = sAh + QTILE;
        const uint32_t sBh = sAl + QTILE;
        const uint32_t sBl = sBh + QTILE;

#pragma unroll
        for (int ks = 0; ks < 2; ++ks) {
            const uint32_t kso = (uint32_t)ks * 32;
            uint32_t a_hi[2][4], a_lo[2][4];
#pragma unroll
            for (int mt = 0; mt < 2; mt++) {
                uint32_t base = (uint32_t)(m0w + 16 * mt) * QROWB + kso + lm_off;
                ldm_x4(a_hi[mt], sAh + base);
                ldm_x4(a_lo[mt], sAl + base);
            }
#pragma unroll
            for (int bp = 0; bp < 4; bp++) {
                uint32_t base = (uint32_t)(n0w + 16 * bp) * QROWB + kso + lm_off;
                uint32_t b_hi[4], b_lo[4];
                ldm_x4(b_hi, sBh + base);
                ldm_x4(b_lo, sBl + base);
                // term-major: accumulator reuse distance 4
#pragma unroll
                for (int half = 0; half < 2; half++)
#pragma unroll
                    for (int mt = 0; mt < 2; mt++)
                        mma_bf16(acc[mt][2*bp+half], a_hi[mt], b_hi[half], b_hi[half + 2]);
#pragma unroll
                for (int half = 0; half < 2; half++)
#pragma unroll
                    for (int mt = 0; mt < 2; mt++)
                        mma_bf16(acc[mt][2*bp+half], a_lo[mt], b_hi[half], b_hi[half + 2]);
#pragma unroll
                for (int half = 0; half < 2; half++)
#pragma unroll
                    for (int mt = 0; mt < 2; mt++)
                        mma_bf16(acc[mt][2*bp+half], a_hi[mt], b_lo[half], b_lo[half + 2]);
            }
        }
    }

#pragma unroll
    for (int mt = 0; mt < 2; mt++) {
#pragma unroll
        for (int nt = 0; nt < 8; nt++) {
            int row0 = m0 + m0w + 16 * mt + (lane >> 2);
            int col  = o0 + n0w + 8 * nt + 2 * (lane & 3);
            int h = col / HD, d = col & (HD - 1);
            float b0 = bias[col], b1 = bias[col + 1];
            {
                int b_ = row0 >> 11, n = row0 & (NN - 1);
                size_t idx = (((size_t)b_ * NH + h) * NN + n) * HD + d;
                uint32_t hh, ll;
                split2((acc[mt][nt][0] + b0) * osc, (acc[mt][nt][1] + b1) * osc, hh, ll);
                *(uint32_t*)(dh + idx) = hh;
                *(uint32_t*)(dl + idx) = ll;
            }
            {
                int row1 = row0 + 8;
                int b_ = row1 >> 11, n = row1 & (NN - 1);
                size_t idx = (((size_t)b_ * NH + h) * NN + n) * HD + d;
                uint32_t hh, ll;
                split2((acc[mt][nt][2] + b0) * osc, (acc[mt][nt][3] + b1) * osc, hh, ll);
                *(uint32_t*)(dh + idx) = hh;
                *(uint32_t*)(dl + idx) = ll;
            }
        }
    }
}

// ===================== Flash attention: cp.async + term-major MMA =====================
__global__ __launch_bounds__(256, 2) void attn_mma(float* __restrict__ out)
{
    extern __shared__ char smem[];
    const uint32_t sbase = smem_u32(smem);
    const uint32_t sQhi = sbase;
    const uint32_t sQlo = sbase + TILEB;
    const uint32_t sKV0 = sbase + 2 * TILEB;

    const int b = blockIdx.z, h = blockIdx.y;
    const int q0 = blockIdx.x * 128;
    const size_t hb = ((size_t)b * NH + h) * NN;
    const __nv_bfloat16* qh = g_qh + hb * HD;
    const __nv_bfloat16* ql = g_ql + hb * HD;
    const __nv_bfloat16* kh = g_kh + hb * HD;
    const __nv_bfloat16* kl = g_kl + hb * HD;
    const __nv_bfloat16* vh = g_vh + hb * HD;
    const __nv_bfloat16* vl = g_vl + hb * HD;

    const int tid = threadIdx.x;
    const int wid = tid >> 5, lane = tid & 31;
    const uint32_t lm_off = (uint32_t)(lane & 15) * RPB + (uint32_t)(lane >> 4) * 16;
    const int seg = tid & 7;
    const int rbase = tid >> 3;

    {
#pragma unroll
        for (int p = 0; p < 8; ++p) {
            const int arr = p >> 1;
            int r = (p & 1) * 32 + rbase;
            const __nv_bfloat16* g = (arr == 0) ? kh : (arr == 1) ? kl
                                   : (arr == 2) ? vh : vl;
            cpa16(sKV0 + (uint32_t)(arr * KTILEB + r * RPB + seg * 16),
                  g + (size_t)r * HD + seg * 8);
        }
        CPA_COMMIT();
    }
#pragma unroll
    for (int p = 0; p < 8; ++p) {
        const int arr = p >> 2;
        int r = (p & 3) * 32 + rbase;
        const __nv_bfloat16* g = arr ? ql : qh;
        uint4 v = *(const uint4*)(g + (size_t)(q0 + r) * HD + seg * 8);
        *(uint4*)(smem + (arr ? TILEB : 0) + r * RPB + seg * 16) = v;
    }

    float o_[8][4];
    float mA = -INFINITY, mB = -INFINITY, lA = 0.f, lB = 0.f;
#pragma unroll
    for (int nt = 0; nt < 8; nt++)
#pragma unroll
        for (int q = 0; q < 4; q++) o_[nt][q] = 0.f;

    const int NT = NN / 64;
    for (int it = 0; it < NT; ++it) {
        const int st = it & 1;
        CPA_WAIT0();
        __syncthreads();

        if (it + 1 < NT) {
            const int j1 = (it + 1) * 64;
            const uint32_t sst = sKV0 + (uint32_t)(((it + 1) & 1) * KSTG);
#pragma unroll
            for (int p = 0; p < 8; ++p) {
                const int arr = p >> 1;
                int r = (p & 1) * 32 + rbase;
                const __nv_bfloat16* g = (arr == 0) ? kh : (arr == 1) ? kl
                                       : (arr == 2) ? vh : vl;
                cpa16(sst + (uint32_t)(arr * KTILEB + r * RPB + seg * 16),
                      g + (size_t)(j1 + r) * HD + seg * 8);
            }
            CPA_COMMIT();
        }

        const uint32_t sKhi = sKV0 + (uint32_t)(st * KSTG);
        const uint32_t sKlo = sKhi + KTILEB;
        const uint32_t sVhi = sKlo + KTILEB;
        const uint32_t sVlo = sVhi + KTILEB;

        // ---- S = Q @ K^T, term-major (chain distance 8) ----
        float s_[8][4];
#pragma unroll
        for (int nt = 0; nt < 8; nt++)
#pragma unroll
            for (int q = 0; q < 4; q++) s_[nt][q] = 0.f;

#pragma unroll
        for (int ks = 0; ks < 4; ++ks) {
            const uint32_t kso = (uint32_t)ks * 32;
            uint32_t ah[4], al[4];
            uint32_t ab = (uint32_t)(wid * 16) * RPB + kso + lm_off;
            ldm_x4(ah, sQhi + ab);
            ldm_x4(al, sQlo + ab);
            uint32_t bf[4][4];
#pragma unroll
            for (int bp = 0; bp < 4; bp++)
                ldm_x4(bf[bp], sKhi + (uint32_t)(16 * bp) * RPB + kso + lm_off);
#pragma unroll
            for (int bp = 0; bp < 4; bp++)
#pragma unroll
                for (int half = 0; half < 2; half++)
                    mma_bf16(s_[2*bp+half], ah, bf[bp][half], bf[bp][half + 2]);
#pragma unroll
            for (int bp = 0; bp < 4; bp++)
#pragma unroll
                for (int half = 0; half < 2; half++)
                    mma_bf16(s_[2*bp+half], al, bf[bp][half], bf[bp][half + 2]);
#pragma unroll
            for (int bp = 0; bp < 4; bp++)
                ldm_x4(bf[bp], sKlo + (uint32_t)(16 * bp) * RPB + kso + lm_off);
#pragma unroll
            for (int bp = 0; bp < 4; bp++)
#pragma unroll
                for (int half = 0; half < 2; half++)
                    mma_bf16(s_[2*bp+half], ah, bf[bp][half], bf[bp][half + 2]);
        }

        // ---- online softmax ----
        float mlA = -INFINITY, mlB = -INFINITY;
#pragma unroll
        for (int nt = 0; nt < 8; nt++) {
            mlA = fmaxf(mlA, fmaxf(s_[nt][0], s_[nt][1]));
            mlB = fmaxf(mlB, fmaxf(s_[nt][2], s_[nt][3]));
        }
#pragma unroll
        for (int off = 1; off <= 2; off <<= 1) {
            mlA = fmaxf(mlA, __shfl_xor_sync(0xffffffffu, mlA, off));
            mlB = fmaxf(mlB, __shfl_xor_sync(0xffffffffu, mlB, off));
        }
        float mnA = fmaxf(mA, mlA), mnB = fmaxf(mB, mlB);
        float aAl = ex2f(mA - mnA), aBl = ex2f(mB - mnB);
        mA = mnA; mB = mnB;
        float sumA = 0.f, sumB = 0.f;
#pragma unroll
        for (int nt = 0; nt < 8; nt++) {
            s_[nt][0] = ex2f(s_[nt][0] - mA);
            s_[nt][1] = ex2f(s_[nt][1] - mA);
            s_[nt][2] = ex2f(s_[nt][2] - mB);
            s_[nt][3] = ex2f(s_[nt][3] - mB);
            sumA += s_[nt][0] + s_[nt][1];
            sumB += s_[nt][2] + s_[nt][3];
            o_[nt][0] *= aAl; o_[nt][1] *= aAl;
            o_[nt][2] *= aBl; o_[nt][3] *= aBl;
        }
#pragma unroll
        for (int off = 1; off <= 2; off <<= 1) {
            sumA += __shfl_xor_sync(0xffffffffu, sumA, off);
            sumB += __shfl_xor_sync(0xffffffffu, sumB, off);
        }
        lA = lA * aAl + sumA;
        lB = lB * aBl + sumB;

        // ---- O += P @ V, term-major (chain distance 8) ----
#pragma unroll
        for (int t = 0; t < 4; t++) {
            uint32_t pah[4], pal[4];
#pragma unroll
            for (int i = 0; i < 4; i++) {
                const float* src = (i < 2) ? s_[2 * t] : s_[2 * t + 1];
                float x0 = src[(i & 1) ? 2 : 0];
                float x1 = src[(i & 1) ? 3 : 1];
                split2(x0, x1, pah[i], pal[i]);
            }
            uint32_t vf[4][4];
            const uint32_t vrow = (uint32_t)(16 * t + (lane & 7) + ((lane >> 3) & 1) * 8) * RPB
                                + (uint32_t)(lane >> 4) * 16;
#pragma unroll
            for (int db = 0; db < 4; db++)
                ldm_x4_t(vf[db], sVhi + vrow + (uint32_t)(32 * db));
#pragma unroll
            for (int db = 0; db < 4; db++)
#pragma unroll
                for (int half = 0; half < 2; half++)
                    mma_bf16(o_[2*db+half], pah, vf[db][2*half], vf[db][2*half + 1]);
#pragma unroll
            for (int db = 0; db < 4; db++)
#pragma unroll
                for (int half = 0; half < 2; half++)
                    mma_bf16(o_[2*db+half], pal, vf[db][2*half], vf[db][2*half + 1]);
#pragma unroll
            for (int db = 0; db < 4; db++)
                ldm_x4_t(vf[db], sVlo + vrow + (uint32_t)(32 * db));
#pragma unroll
            for (int db = 0; db < 4; db++)
#pragma unroll
                for (int half = 0; half < 2; half++)
                    mma_bf16(o_[2*db+half], pah, vf[db][2*half], vf[db][2*half + 1]);
        }
    }

    // ---- epilogue ----
    const int rowA = q0 + 16 * wid + (lane >> 2);
    const int rowB = rowA + 8;
    const float invA = 1.f / lA, invB = 1.f / lB;
#pragma unroll
    for (int nt = 0; nt < 8; nt++) {
        int d0 = 8 * nt + 2 * (lane & 3);
        float2 vA = make_float2(o_[nt][0] * invA, o_[nt][1] * invA);
        float2 vB = make_float2(o_[nt][2] * invB, o_[nt][3] * invB);
        *(float2*)&out[((size_t)b * NN + rowA) * DIM + h * HD + d0] = vA;
        *(float2*)&out[((size_t)b * NN + rowB) * DIM + h * HD + d0] = vB;
    }
}

extern "C" void kernel_launch(void* const* d_in, const int* in_sizes, int n_in,
                              void* d_out, int out_size)
{
    (void)in_sizes; (void)n_in; (void)out_size;
    const float* x  = (const float*)d_in[0];
    const float* wq = (const float*)d_in[1];
    const float* bq = (const float*)d_in[2];
    const float* wk = (const float*)d_in[3];
    const float* bk = (const float*)d_in[4];
    const float* wv = (const float*)d_in[5];
    const float* bv = (const float*)d_in[6];
    float* out = (float*)d_out;

    {
        int n4x = MROWS * DIM / 4;
        __nv_bfloat16 *xh, *xl, *wqh, *wql, *wkh, *wkl, *wvh, *wvl;
        cudaGetSymbolAddress((void**)&xh, g_xh);
        cudaGetSymbolAddress((void**)&xl, g_xl);
        cudaGetSymbolAddress((void**)&wqh, g_wqh);
        cudaGetSymbolAddress((void**)&wql, g_wql);
        cudaGetSymbolAddress((void**)&wkh, g_wkh);
        cudaGetSymbolAddress((void**)&wkl, g_wkl);
        cudaGetSymbolAddress((void**)&wvh, g_wvh);
        cudaGetSymbolAddress((void**)&wvl, g_wvl);
        split_f32<<<(n4x + 255) / 256, 256>>>((const float4*)x, (uint2*)xh, (uint2*)xl, n4x);
        int n4w = DIM * DIM / 4;
        split_f32<<<(n4w + 255) / 256, 256>>>((const float4*)wq, (uint2*)wqh, (uint2*)wql, n4w);
        split_f32<<<(n4w + 255) / 256, 256>>>((const float4*)wk, (uint2*)wkh, (uint2*)wkl, n4w);
        split_f32<<<(n4w + 255) / 256, 256>>>((const float4*)wv, (uint2*)wvh, (uint2*)wvl, n4w);
    }

    size_t q_smem = 2 * (size_t)QSTG;   // 81920 B
    cudaFuncSetAttribute(qkv_mma, cudaFuncAttributeMaxDynamicSharedMemorySize,
                         (int)q_smem);
    dim3 g1(DIM / 128, MROWS / 128, 3);
    qkv_mma<<<g1, 256, q_smem>>>(bq, bk, bv);

    size_t a_smem = 2 * (size_t)TILEB + 2 * (size_t)KSTG;   // 110592 B
    cudaFuncSetAttribute(attn_mma, cudaFuncAttributeMaxDynamicSharedMemorySize,
                         (int)a_smem);
    dim3 g2(NN / 128, NH, BB);
    attn_mma<<<g2, 256, a_smem>>>(out);
}

// round 14
// speedup vs baseline: 1.4228x; 1.4222x over previous
#include <cuda_runtime.h>
#include <cuda_fp16.h>
#include <math.h>
#include <stdint.h>

#define BB 4
#define NN 2048
#define DIM 768
#define NH 12
#define HD 64
#define MROWS (BB*NN)   // 8192
#define SZT (BB*NH*NN*HD)

// scratch: Q split hi/lo fp16; K,V single fp16; [b,h,n,d] layout
__device__ __align__(16) __half g_qh[SZT], g_ql[SZT];
__device__ __align__(16) __half g_k16[SZT];
__device__ __align__(16) __half g_v16[SZT];
// pre-converted inputs: x split hi/lo, weights single fp16
__device__ __align__(16) __half g_xh[MROWS*DIM], g_xl[MROWS*DIM];
__device__ __align__(16) __half g_wq16[DIM*DIM], g_wk16[DIM*DIM], g_wv16[DIM*DIM];

// ====================== helpers ======================
__device__ __forceinline__ uint32_t smem_u32(const void* p) {
    uint32_t a;
    asm("{ .reg .u64 t; cvta.to.shared.u64 t, %1; cvt.u32.u64 %0, t; }"
        : "=r"(a) : "l"(p));
    return a;
}
__device__ __forceinline__ void ldm_x4(uint32_t* r, uint32_t addr) {
    asm volatile("ldmatrix.sync.aligned.m8n8.x4.shared.b16 {%0,%1,%2,%3}, [%4];"
                 : "=r"(r[0]), "=r"(r[1]), "=r"(r[2]), "=r"(r[3]) : "r"(addr));
}
__device__ __forceinline__ void ldm_x4_t(uint32_t* r, uint32_t addr) {
    asm volatile("ldmatrix.sync.aligned.m8n8.x4.trans.shared.b16 {%0,%1,%2,%3}, [%4];"
                 : "=r"(r[0]), "=r"(r[1]), "=r"(r[2]), "=r"(r[3]) : "r"(addr));
}
__device__ __forceinline__ void mma_f16(float* c, const uint32_t* a,
                                        uint32_t b0, uint32_t b1) {
    asm volatile(
        "mma.sync.aligned.m16n8k16.row.col.f32.f16.f16.f32 "
        "{%0,%1,%2,%3}, {%4,%5,%6,%7}, {%8,%9}, {%0,%1,%2,%3};"
        : "+f"(c[0]), "+f"(c[1]), "+f"(c[2]), "+f"(c[3])
        : "r"(a[0]), "r"(a[1]), "r"(a[2]), "r"(a[3]), "r"(b0), "r"(b1));
}
__device__ __forceinline__ float ex2f(float x) {
    float y;
    asm("ex2.approx.ftz.f32 %0, %1;" : "=f"(y) : "f"(x));
    return y;
}
// fp16 split: h = rn(x), l = exact remainder (|l| <= 2^-12 |x|)
__device__ __forceinline__ void split2h(float x0, float x1, uint32_t& h, uint32_t& l) {
    __half2 hh = __floats2half2_rn(x0, x1);
    float2 hf = __half22float2(hh);
    __half2 ll = __floats2half2_rn(x0 - hf.x, x1 - hf.y);
    h = *(uint32_t*)&hh;
    l = *(uint32_t*)&ll;
}
__device__ __forceinline__ void cpa16(uint32_t s, const void* g) {
    asm volatile("cp.async.cg.shared.global [%0], [%1], 16;"
                 :: "r"(s), "l"(g) : "memory");
}
#define CPA_COMMIT() asm volatile("cp.async.commit_group;" ::: "memory")
#define CPA_WAIT0()  asm volatile("cp.async.wait_group 0;" ::: "memory")
#define CPA_WAIT1()  asm volatile("cp.async.wait_group 1;" ::: "memory")

#define RPB 144
#define TILEB (128*RPB)           // 18432 B (128 rows x 64 fp16 + pad)
#define KTILEB (64*RPB)           // 9216 B
#define KSTG2 (2*KTILEB)          // K + V per stage

// ===================== input conversion =====================
__global__ __launch_bounds__(256) void split_x(
    const float4* __restrict__ src, uint2* __restrict__ dh,
    uint2* __restrict__ dl, int n4)
{
    int i = blockIdx.x * 256 + threadIdx.x;
    if (i >= n4) return;
    float4 v = src[i];
    uint32_t h0, l0, h1, l1;
    split2h(v.x, v.y, h0, l0);
    split2h(v.z, v.w, h1, l1);
    dh[i] = make_uint2(h0, h1);
    dl[i] = make_uint2(l0, l1);
}
__global__ __launch_bounds__(256) void cvt_w(
    const float4* __restrict__ src, uint2* __restrict__ dst, int n4)
{
    int i = blockIdx.x * 256 + threadIdx.x;
    if (i >= n4) return;
    float4 v = src[i];
    __half2 a = __floats2half2_rn(v.x, v.y);
    __half2 b = __floats2half2_rn(v.z, v.w);
    dst[i] = make_uint2(*(uint32_t*)&a, *(uint32_t*)&b);
}

// ===================== QKV GEMM: fp16 2-term, 3-stage cp.async =====================
#define QCH 32
#define QROWB 80                  // 32 fp16 = 64 B + 16 pad
#define QTILE (128*QROWB)         // 10240 B
#define QSTG3 (3*QTILE)           // Ah, Al, Bh per stage

__global__ __launch_bounds__(256, 2) void qkv_mma(
    const float* __restrict__ bq, const float* __restrict__ bk,
    const float* __restrict__ bv)
{
    extern __shared__ char smem[];
    const uint32_t sbase = smem_u32(smem);

    const int mat = blockIdx.z;
    const __half* w16 = (mat == 0) ? g_wq16 : (mat == 1) ? g_wk16 : g_wv16;
    const float* bias = (mat == 0) ? bq : (mat == 1) ? bk : bv;
    __half* dh = (mat == 0) ? g_qh : (mat == 1) ? g_k16 : g_v16;
    const float osc = (mat == 0) ? 0.125f * 1.44269504f : 1.0f;

    const int m0 = blockIdx.y * 128;
    const int o0 = blockIdx.x * 128;
    const int tid = threadIdx.x;
    const int wid = tid >> 5, lane = tid & 31;
    const int warpM = wid & 3, warpN = wid >> 2;
    const int m0w = warpM * 32, n0w = warpN * 64;
    const uint32_t lm_off = (uint32_t)(lane & 15) * QROWB + (uint32_t)(lane >> 4) * 16;
    const int lrow = tid >> 2, lseg = tid & 3;

    float acc[2][8][4];
#pragma unroll
    for (int mt = 0; mt < 2; mt++)
#pragma unroll
        for (int nt = 0; nt < 8; nt++)
#pragma unroll
            for (int q = 0; q < 4; q++) acc[mt][nt][q] = 0.f;

    const int NC = DIM / QCH;   // 24 chunks

    // issue chunks 0 and 1
#pragma unroll
    for (int c0 = 0; c0 < 2; ++c0) {
        const uint32_t ss = sbase + (uint32_t)(c0 * QSTG3);
        const int kb = c0 * QCH;
#pragma unroll
        for (int p = 0; p < 6; ++p) {
            int arr = p >> 1;
            int row = (p & 1) * 64 + lrow;
            const __half* g =
                (arr == 0) ? g_xh + (size_t)(m0 + row) * DIM :
                (arr == 1) ? g_xl + (size_t)(m0 + row) * DIM :
                             w16 + (size_t)(o0 + row) * DIM;
            cpa16(ss + (uint32_t)(arr * QTILE + row * QROWB + lseg * 16),
                  g + kb + lseg * 8);
        }
        CPA_COMMIT();
    }

    for (int c = 0; c < NC; ++c) {
        if (c + 1 < NC) { CPA_WAIT1(); } else { CPA_WAIT0(); }
        __syncthreads();

        if (c + 2 < NC) {
            const int kb = (c + 2) * QCH;
            const uint32_t ss = sbase + (uint32_t)(((c + 2) % 3) * QSTG3);
#pragma unroll
            for (int p = 0; p < 6; ++p) {
                int arr = p >> 1;
                int row = (p & 1) * 64 + lrow;
                const __half* g =
                    (arr == 0) ? g_xh + (size_t)(m0 + row) * DIM :
                    (arr == 1) ? g_xl + (size_t)(m0 + row) * DIM :
                                 w16 + (size_t)(o0 + row) * DIM;
                cpa16(ss + (uint32_t)(arr * QTILE + row * QROWB + lseg * 16),
                      g + kb + lseg * 8);
            }
            CPA_COMMIT();
        }

        const uint32_t sAh = sbase + (uint32_t)((c % 3) * QSTG3);
        const uint32_t sAl = sAh + QTILE;
        const uint32_t sBh = sAl + QTILE;

#pragma unroll
        for (int ks = 0; ks < 2; ++ks) {
            const uint32_t kso = (uint32_t)ks * 32;
            uint32_t a_hi[2][4], a_lo[2][4];
#pragma unroll
            for (int mt = 0; mt < 2; mt++) {
                uint32_t base = (uint32_t)(m0w + 16 * mt) * QROWB + kso + lm_off;
                ldm_x4(a_hi[mt], sAh + base);
                ldm_x4(a_lo[mt], sAl + base);
            }
            uint32_t bf[4][4];
#pragma unroll
            for (int bp = 0; bp < 4; bp++)
                ldm_x4(bf[bp], sBh + (uint32_t)(n0w + 16 * bp) * QROWB + kso + lm_off);
#pragma unroll
            for (int bp = 0; bp < 4; bp++)
#pragma unroll
                for (int half = 0; half < 2; half++)
#pragma unroll
                    for (int mt = 0; mt < 2; mt++)
                        mma_f16(acc[mt][2*bp+half], a_hi[mt], bf[bp][half], bf[bp][half + 2]);
#pragma unroll
            for (int bp = 0; bp < 4; bp++)
#pragma unroll
                for (int half = 0; half < 2; half++)
#pragma unroll
                    for (int mt = 0; mt < 2; mt++)
                        mma_f16(acc[mt][2*bp+half], a_lo[mt], bf[bp][half], bf[bp][half + 2]);
        }
    }

    // Epilogue: bias (+Q scale), fp16 store; Q additionally stores lo residual
#pragma unroll
    for (int mt = 0; mt < 2; mt++) {
#pragma unroll
        for (int nt = 0; nt < 8; nt++) {
            int row0 = m0 + m0w + 16 * mt + (lane >> 2);
            int col  = o0 + n0w + 8 * nt + 2 * (lane & 3);
            int h = col / HD, d = col & (HD - 1);
            float b0 = bias[col], b1 = bias[col + 1];
#pragma unroll
            for (int half = 0; half < 2; half++) {
                int row = row0 + 8 * half;
                int b_ = row >> 11, n = row & (NN - 1);
                size_t idx = (((size_t)b_ * NH + h) * NN + n) * HD + d;
                float y0 = (acc[mt][nt][2*half]     + b0) * osc;
                float y1 = (acc[mt][nt][2*half + 1] + b1) * osc;
                __half2 hp = __floats2half2_rn(y0, y1);
                *(uint32_t*)(dh + idx) = *(uint32_t*)&hp;
                if (mat == 0) {
                    float2 hf = __half22float2(hp);
                    __half2 lp = __floats2half2_rn(y0 - hf.x, y1 - hf.y);
                    *(uint32_t*)(g_ql + idx) = *(uint32_t*)&lp;
                }
            }
        }
    }
}

// ===================== Flash attention: fp16 2-term, 3-stage cp.async =====================
__global__ __launch_bounds__(256, 2) void attn_mma(float* __restrict__ out)
{
    extern __shared__ char smem[];
    const uint32_t sbase = smem_u32(smem);
    const uint32_t sQhi = sbase;
    const uint32_t sQlo = sbase + TILEB;
    const uint32_t sKV0 = sbase + 2 * TILEB;   // stage s: sKV0 + s*KSTG2 (K then V)

    const int b = blockIdx.z, h = blockIdx.y;
    const int q0 = blockIdx.x * 128;
    const size_t hb = ((size_t)b * NH + h) * NN;
    const __half* qh = g_qh + hb * HD;
    const __half* ql = g_ql + hb * HD;
    const __half* k16 = g_k16 + hb * HD;
    const __half* v16 = g_v16 + hb * HD;

    const int tid = threadIdx.x;
    const int wid = tid >> 5, lane = tid & 31;
    const uint32_t lm_off = (uint32_t)(lane & 15) * RPB + (uint32_t)(lane >> 4) * 16;
    const int seg = tid & 7;
    const int rbase = tid >> 3;

    // issue tiles 0,1; copy Q
#pragma unroll
    for (int t0 = 0; t0 < 2; ++t0) {
        const uint32_t ss = sKV0 + (uint32_t)(t0 * KSTG2);
        const int j0 = t0 * 64;
#pragma unroll
        for (int p = 0; p < 4; ++p) {
            const int arr = p >> 1;           // 0=K 1=V
            int r = (p & 1) * 32 + rbase;
            const __half* g = arr ? v16 : k16;
            cpa16(ss + (uint32_t)(arr * KTILEB + r * RPB + seg * 16),
                  g + (size_t)(j0 + r) * HD + seg * 8);
        }
        CPA_COMMIT();
    }
#pragma unroll
    for (int p = 0; p < 8; ++p) {
        const int arr = p >> 2;               // 0=Qhi 1=Qlo
        int r = (p & 3) * 32 + rbase;
        const __half* g = arr ? ql : qh;
        uint4 v = *(const uint4*)(g + (size_t)(q0 + r) * HD + seg * 8);
        *(uint4*)(smem + (arr ? TILEB : 0) + r * RPB + seg * 16) = v;
    }

    float o_[8][4];
    float mA = -INFINITY, mB = -INFINITY, lA = 0.f, lB = 0.f;
#pragma unroll
    for (int nt = 0; nt < 8; nt++)
#pragma unroll
        for (int q = 0; q < 4; q++) o_[nt][q] = 0.f;

    const int NT = NN / 64;   // 32
    for (int it = 0; it < NT; ++it) {
        if (it + 1 < NT) { CPA_WAIT1(); } else { CPA_WAIT0(); }
        __syncthreads();

        if (it + 2 < NT) {
            const int j2 = (it + 2) * 64;
            const uint32_t sst = sKV0 + (uint32_t)(((it + 2) % 3) * KSTG2);
#pragma unroll
            for (int p = 0; p < 4; ++p) {
                const int arr = p >> 1;
                int r = (p & 1) * 32 + rbase;
                const __half* g = arr ? v16 : k16;
                cpa16(sst + (uint32_t)(arr * KTILEB + r * RPB + seg * 16),
                      g + (size_t)(j2 + r) * HD + seg * 8);
            }
            CPA_COMMIT();
        }

        const uint32_t sK = sKV0 + (uint32_t)((it % 3) * KSTG2);
        const uint32_t sV = sK + KTILEB;

        // ---- S = (Qh+Ql) @ Kh^T, 2-term ----
        float s_[8][4];
#pragma unroll
        for (int nt = 0; nt < 8; nt++)
#pragma unroll
            for (int q = 0; q < 4; q++) s_[nt][q] = 0.f;

#pragma unroll
        for (int ks = 0; ks < 4; ++ks) {
            const uint32_t kso = (uint32_t)ks * 32;
            uint32_t ah[4], al[4];
            uint32_t ab = (uint32_t)(wid * 16) * RPB + kso + lm_off;
            ldm_x4(ah, sQhi + ab);
            ldm_x4(al, sQlo + ab);
            uint32_t bf[4][4];
#pragma unroll
            for (int bp = 0; bp < 4; bp++)
                ldm_x4(bf[bp], sK + (uint32_t)(16 * bp) * RPB + kso + lm_off);
#pragma unroll
            for (int bp = 0; bp < 4; bp++)
#pragma unroll
                for (int half = 0; half < 2; half++)
                    mma_f16(s_[2*bp+half], ah, bf[bp][half], bf[bp][half + 2]);
#pragma unroll
            for (int bp = 0; bp < 4; bp++)
#pragma unroll
                for (int half = 0; half < 2; half++)
                    mma_f16(s_[2*bp+half], al, bf[bp][half], bf[bp][half + 2]);
        }

        // ---- online softmax (log2 domain; Q pre-scaled) ----
        float mlA = -INFINITY, mlB = -INFINITY;
#pragma unroll
        for (int nt = 0; nt < 8; nt++) {
            mlA = fmaxf(mlA, fmaxf(s_[nt][0], s_[nt][1]));
            mlB = fmaxf(mlB, fmaxf(s_[nt][2], s_[nt][3]));
        }
#pragma unroll
        for (int off = 1; off <= 2; off <<= 1) {
            mlA = fmaxf(mlA, __shfl_xor_sync(0xffffffffu, mlA, off));
            mlB = fmaxf(mlB, __shfl_xor_sync(0xffffffffu, mlB, off));
        }
        float mnA = fmaxf(mA, mlA), mnB = fmaxf(mB, mlB);
        float aAl = ex2f(mA - mnA), aBl = ex2f(mB - mnB);
        mA = mnA; mB = mnB;
        float sumA = 0.f, sumB = 0.f;
#pragma unroll
        for (int nt = 0; nt < 8; nt++) {
            s_[nt][0] = ex2f(s_[nt][0] - mA);
            s_[nt][1] = ex2f(s_[nt][1] - mA);
            s_[nt][2] = ex2f(s_[nt][2] - mB);
            s_[nt][3] = ex2f(s_[nt][3] - mB);
            sumA += s_[nt][0] + s_[nt][1];
            sumB += s_[nt][2] + s_[nt][3];
            o_[nt][0] *= aAl; o_[nt][1] *= aAl;
            o_[nt][2] *= aBl; o_[nt][3] *= aBl;
        }
#pragma unroll
        for (int off = 1; off <= 2; off <<= 1) {
            sumA += __shfl_xor_sync(0xffffffffu, sumA, off);
            sumB += __shfl_xor_sync(0xffffffffu, sumB, off);
        }
        lA = lA * aAl + sumA;
        lB = lB * aBl + sumB;

        // ---- O += (Ph+Pl) @ Vh, 2-term ----
#pragma unroll
        for (int t = 0; t < 4; t++) {
            uint32_t pah[4], pal[4];
#pragma unroll
            for (int i = 0; i < 4; i++) {
                const float* src = (i < 2) ? s_[2 * t] : s_[2 * t + 1];
                float x0 = src[(i & 1) ? 2 : 0];
                float x1 = src[(i & 1) ? 3 : 1];
                split2h(x0, x1, pah[i], pal[i]);
            }
            uint32_t vf[4][4];
            const uint32_t vrow = (uint32_t)(16 * t + (lane & 7) + ((lane >> 3) & 1) * 8) * RPB
                                + (uint32_t)(lane >> 4) * 16;
#pragma unroll
            for (int db = 0; db < 4; db++)
                ldm_x4_t(vf[db], sV + vrow + (uint32_t)(32 * db));
#pragma unroll
            for (int db = 0; db < 4; db++)
#pragma unroll
                for (int half = 0; half < 2; half++)
                    mma_f16(o_[2*db+half], pah, vf[db][2*half], vf[db][2*half + 1]);
#pragma unroll
            for (int db = 0; db < 4; db++)
#pragma unroll
                for (int half = 0; half < 2; half++)
                    mma_f16(o_[2*db+half], pal, vf[db][2*half], vf[db][2*half + 1]);
        }
    }

    // ---- epilogue ----
    const int rowA = q0 + 16 * wid + (lane >> 2);
    const int rowB = rowA + 8;
    const float invA = 1.f / lA, invB = 1.f / lB;
#pragma unroll
    for (int nt = 0; nt < 8; nt++) {
        int d0 = 8 * nt + 2 * (lane & 3);
        float2 vA = make_float2(o_[nt][0] * invA, o_[nt][1] * invA);
        float2 vB = make_float2(o_[nt][2] * invB, o_[nt][3] * invB);
        *(float2*)&out[((size_t)b * NN + rowA) * DIM + h * HD + d0] = vA;
        *(float2*)&out[((size_t)b * NN + rowB) * DIM + h * HD + d0] = vB;
    }
}

extern "C" void kernel_launch(void* const* d_in, const int* in_sizes, int n_in,
                              void* d_out, int out_size)
{
    (void)in_sizes; (void)n_in; (void)out_size;
    const float* x  = (const float*)d_in[0];
    const float* wq = (const float*)d_in[1];
    const float* bq = (const float*)d_in[2];
    const float* wk = (const float*)d_in[3];
    const float* bk = (const float*)d_in[4];
    const float* wv = (const float*)d_in[5];
    const float* bv = (const float*)d_in[6];
    float* out = (float*)d_out;

    // 1. convert inputs
    {
        __half *xh, *xl, *wq16, *wk16, *wv16;
        cudaGetSymbolAddress((void**)&xh, g_xh);
        cudaGetSymbolAddress((void**)&xl, g_xl);
        cudaGetSymbolAddress((void**)&wq16, g_wq16);
        cudaGetSymbolAddress((void**)&wk16, g_wk16);
        cudaGetSymbolAddress((void**)&wv16, g_wv16);
        int n4x = MROWS * DIM / 4;
        split_x<<<(n4x + 255) / 256, 256>>>((const float4*)x, (uint2*)xh, (uint2*)xl, n4x);
        int n4w = DIM * DIM / 4;
        cvt_w<<<(n4w + 255) / 256, 256>>>((const float4*)wq, (uint2*)wq16, n4w);
        cvt_w<<<(n4w + 255) / 256, 256>>>((const float4*)wk, (uint2*)wk16, n4w);
        cvt_w<<<(n4w + 255) / 256, 256>>>((const float4*)wv, (uint2*)wv16, n4w);
    }

    // 2. QKV projections
    size_t q_smem = 3 * (size_t)QSTG3;   // 92160 B
    cudaFuncSetAttribute(qkv_mma, cudaFuncAttributeMaxDynamicSharedMemorySize,
                         (int)q_smem);
    dim3 g1(DIM / 128, MROWS / 128, 3);
    qkv_mma<<<g1, 256, q_smem>>>(bq, bk, bv);

    // 3. attention
    size_t a_smem = 2 * (size_t)TILEB + 3 * (size_t)KSTG2;   // 92160 B
    cudaFuncSetAttribute(attn_mma, cudaFuncAttributeMaxDynamicSharedMemorySize,
                         (int)a_smem);
    dim3 g2(NN / 128, NH, BB);
    attn_mma<<<g2, 256, a_smem>>>(out);
}

// round 15
// speedup vs baseline: 1.6063x; 1.1290x over previous
#include <cuda_runtime.h>
#include <cuda_fp16.h>
#include <math.h>
#include <stdint.h>

#define BB 4
#define NN 2048
#define DIM 768
#define NH 12
#define HD 64
#define MROWS (BB*NN)   // 8192
#define SZT (BB*NH*NN*HD)

// scratch: Q split hi/lo fp16; K,V single fp16; [b,h,n,d] layout
__device__ __align__(16) __half g_qh[SZT], g_ql[SZT];
__device__ __align__(16) __half g_k16[SZT];
__device__ __align__(16) __half g_v16[SZT];
// pre-converted inputs: x split hi/lo, weights single fp16
__device__ __align__(16) __half g_xh[MROWS*DIM], g_xl[MROWS*DIM];
__device__ __align__(16) __half g_wq16[DIM*DIM], g_wk16[DIM*DIM], g_wv16[DIM*DIM];

// ====================== helpers ======================
__device__ __forceinline__ uint32_t smem_u32(const void* p) {
    uint32_t a;
    asm("{ .reg .u64 t; cvta.to.shared.u64 t, %1; cvt.u32.u64 %0, t; }"
        : "=r"(a) : "l"(p));
    return a;
}
__device__ __forceinline__ void ldm_x4(uint32_t* r, uint32_t addr) {
    asm volatile("ldmatrix.sync.aligned.m8n8.x4.shared.b16 {%0,%1,%2,%3}, [%4];"
                 : "=r"(r[0]), "=r"(r[1]), "=r"(r[2]), "=r"(r[3]) : "r"(addr));
}
__device__ __forceinline__ void ldm_x4_t(uint32_t* r, uint32_t addr) {
    asm volatile("ldmatrix.sync.aligned.m8n8.x4.trans.shared.b16 {%0,%1,%2,%3}, [%4];"
                 : "=r"(r[0]), "=r"(r[1]), "=r"(r[2]), "=r"(r[3]) : "r"(addr));
}
__device__ __forceinline__ void mma_f16(float* c, const uint32_t* a,
                                        uint32_t b0, uint32_t b1) {
    asm volatile(
        "mma.sync.aligned.m16n8k16.row.col.f32.f16.f16.f32 "
        "{%0,%1,%2,%3}, {%4,%5,%6,%7}, {%8,%9}, {%0,%1,%2,%3};"
        : "+f"(c[0]), "+f"(c[1]), "+f"(c[2]), "+f"(c[3])
        : "r"(a[0]), "r"(a[1]), "r"(a[2]), "r"(a[3]), "r"(b0), "r"(b1));
}
__device__ __forceinline__ float ex2f(float x) {
    float y;
    asm("ex2.approx.ftz.f32 %0, %1;" : "=f"(y) : "f"(x));
    return y;
}
// fp16 split: h = rn(x), l = exact remainder (|l| <= 2^-12 |x|)
__device__ __forceinline__ void split2h(float x0, float x1, uint32_t& h, uint32_t& l) {
    __half2 hh = __floats2half2_rn(x0, x1);
    float2 hf = __half22float2(hh);
    __half2 ll = __floats2half2_rn(x0 - hf.x, x1 - hf.y);
    h = *(uint32_t*)&hh;
    l = *(uint32_t*)&ll;
}
__device__ __forceinline__ uint32_t pkh2(float x0, float x1) {
    __half2 hh = __floats2half2_rn(x0, x1);
    return *(uint32_t*)&hh;
}
__device__ __forceinline__ void cpa16(uint32_t s, const void* g) {
    asm volatile("cp.async.cg.shared.global [%0], [%1], 16;"
                 :: "r"(s), "l"(g) : "memory");
}
#define CPA_COMMIT() asm volatile("cp.async.commit_group;" ::: "memory")
#define CPA_WAIT0()  asm volatile("cp.async.wait_group 0;" ::: "memory")
#define CPA_WAIT1()  asm volatile("cp.async.wait_group 1;" ::: "memory")

#define RPB 144
#define TILEB (128*RPB)           // 18432 B
#define KTILEB (64*RPB)           // 9216 B
#define KSTG2 (2*KTILEB)          // K + V per stage

// ===================== input conversion =====================
__global__ __launch_bounds__(256) void split_x(
    const float4* __restrict__ src, uint2* __restrict__ dh,
    uint2* __restrict__ dl, int n4)
{
    int i = blockIdx.x * 256 + threadIdx.x;
    if (i >= n4) return;
    float4 v = src[i];
    uint32_t h0, l0, h1, l1;
    split2h(v.x, v.y, h0, l0);
    split2h(v.z, v.w, h1, l1);
    dh[i] = make_uint2(h0, h1);
    dl[i] = make_uint2(l0, l1);
}
__global__ __launch_bounds__(256) void cvt_w(
    const float4* __restrict__ src, uint2* __restrict__ dst, int n4)
{
    int i = blockIdx.x * 256 + threadIdx.x;
    if (i >= n4) return;
    float4 v = src[i];
    dst[i] = make_uint2(pkh2(v.x, v.y), pkh2(v.z, v.w));
}

// ===================== QKV GEMM: fp16 2-term, 3-stage cp.async =====================
#define QCH 32
#define QROWB 80
#define QTILE (128*QROWB)         // 10240 B
#define QSTG3 (3*QTILE)

__global__ __launch_bounds__(256, 2) void qkv_mma(
    const float* __restrict__ bq, const float* __restrict__ bk,
    const float* __restrict__ bv)
{
    extern __shared__ char smem[];
    const uint32_t sbase = smem_u32(smem);

    const int mat = blockIdx.z;
    const __half* w16 = (mat == 0) ? g_wq16 : (mat == 1) ? g_wk16 : g_wv16;
    const float* bias = (mat == 0) ? bq : (mat == 1) ? bk : bv;
    __half* dh = (mat == 0) ? g_qh : (mat == 1) ? g_k16 : g_v16;
    const float osc = (mat == 0) ? 0.125f * 1.44269504f : 1.0f;

    const int m0 = blockIdx.y * 128;
    const int o0 = blockIdx.x * 128;
    const int tid = threadIdx.x;
    const int wid = tid >> 5, lane = tid & 31;
    const int warpM = wid & 3, warpN = wid >> 2;
    const int m0w = warpM * 32, n0w = warpN * 64;
    const uint32_t lm_off = (uint32_t)(lane & 15) * QROWB + (uint32_t)(lane >> 4) * 16;
    const int lrow = tid >> 2, lseg = tid & 3;

    float acc[2][8][4];
#pragma unroll
    for (int mt = 0; mt < 2; mt++)
#pragma unroll
        for (int nt = 0; nt < 8; nt++)
#pragma unroll
            for (int q = 0; q < 4; q++) acc[mt][nt][q] = 0.f;

    const int NC = DIM / QCH;   // 24

#pragma unroll
    for (int c0 = 0; c0 < 2; ++c0) {
        const uint32_t ss = sbase + (uint32_t)(c0 * QSTG3);
        const int kb = c0 * QCH;
#pragma unroll
        for (int p = 0; p < 6; ++p) {
            int arr = p >> 1;
            int row = (p & 1) * 64 + lrow;
            const __half* g =
                (arr == 0) ? g_xh + (size_t)(m0 + row) * DIM :
                (arr == 1) ? g_xl + (size_t)(m0 + row) * DIM :
                             w16 + (size_t)(o0 + row) * DIM;
            cpa16(ss + (uint32_t)(arr * QTILE + row * QROWB + lseg * 16),
                  g + kb + lseg * 8);
        }
        CPA_COMMIT();
    }

    for (int c = 0; c < NC; ++c) {
        if (c + 1 < NC) { CPA_WAIT1(); } else { CPA_WAIT0(); }
        __syncthreads();

        if (c + 2 < NC) {
            const int kb = (c + 2) * QCH;
            const uint32_t ss = sbase + (uint32_t)(((c + 2) % 3) * QSTG3);
#pragma unroll
            for (int p = 0; p < 6; ++p) {
                int arr = p >> 1;
                int row = (p & 1) * 64 + lrow;
                const __half* g =
                    (arr == 0) ? g_xh + (size_t)(m0 + row) * DIM :
                    (arr == 1) ? g_xl + (size_t)(m0 + row) * DIM :
                                 w16 + (size_t)(o0 + row) * DIM;
                cpa16(ss + (uint32_t)(arr * QTILE + row * QROWB + lseg * 16),
                      g + kb + lseg * 8);
            }
            CPA_COMMIT();
        }

        const uint32_t sAh = sbase + (uint32_t)((c % 3) * QSTG3);
        const uint32_t sAl = sAh + QTILE;
        const uint32_t sBh = sAl + QTILE;

#pragma unroll
        for (int ks = 0; ks < 2; ++ks) {
            const uint32_t kso = (uint32_t)ks * 32;
            uint32_t a_hi[2][4], a_lo[2][4];
#pragma unroll
            for (int mt = 0; mt < 2; mt++) {
                uint32_t base = (uint32_t)(m0w + 16 * mt) * QROWB + kso + lm_off;
                ldm_x4(a_hi[mt], sAh + base);
                ldm_x4(a_lo[mt], sAl + base);
            }
            uint32_t bf[4][4];
#pragma unroll
            for (int bp = 0; bp < 4; bp++)
                ldm_x4(bf[bp], sBh + (uint32_t)(n0w + 16 * bp) * QROWB + kso + lm_off);
#pragma unroll
            for (int bp = 0; bp < 4; bp++)
#pragma unroll
                for (int half = 0; half < 2; half++)
#pragma unroll
                    for (int mt = 0; mt < 2; mt++)
                        mma_f16(acc[mt][2*bp+half], a_hi[mt], bf[bp][half], bf[bp][half + 2]);
#pragma unroll
            for (int bp = 0; bp < 4; bp++)
#pragma unroll
                for (int half = 0; half < 2; half++)
#pragma unroll
                    for (int mt = 0; mt < 2; mt++)
                        mma_f16(acc[mt][2*bp+half], a_lo[mt], bf[bp][half], bf[bp][half + 2]);
        }
    }

#pragma unroll
    for (int mt = 0; mt < 2; mt++) {
#pragma unroll
        for (int nt = 0; nt < 8; nt++) {
            int row0 = m0 + m0w + 16 * mt + (lane >> 2);
            int col  = o0 + n0w + 8 * nt + 2 * (lane & 3);
            int h = col / HD, d = col & (HD - 1);
            float b0 = bias[col], b1 = bias[col + 1];
#pragma unroll
            for (int half = 0; half < 2; half++) {
                int row = row0 + 8 * half;
                int b_ = row >> 11, n = row & (NN - 1);
                size_t idx = (((size_t)b_ * NH + h) * NN + n) * HD + d;
                float y0 = (acc[mt][nt][2*half]     + b0) * osc;
                float y1 = (acc[mt][nt][2*half + 1] + b1) * osc;
                __half2 hp = __floats2half2_rn(y0, y1);
                *(uint32_t*)(dh + idx) = *(uint32_t*)&hp;
                if (mat == 0) {
                    float2 hf = __half22float2(hp);
                    __half2 lp = __floats2half2_rn(y0 - hf.x, y1 - hf.y);
                    *(uint32_t*)(g_ql + idx) = *(uint32_t*)&lp;
                }
            }
        }
    }
}

// ===================== Flash attention: fp16, single-term P@V =====================
__global__ __launch_bounds__(256, 2) void attn_mma(float* __restrict__ out)
{
    extern __shared__ char smem[];
    const uint32_t sbase = smem_u32(smem);
    const uint32_t sQhi = sbase;
    const uint32_t sQlo = sbase + TILEB;
    const uint32_t sKV0 = sbase + 2 * TILEB;

    const int b = blockIdx.z, h = blockIdx.y;
    const int q0 = blockIdx.x * 128;
    const size_t hb = ((size_t)b * NH + h) * NN;
    const __half* qh = g_qh + hb * HD;
    const __half* ql = g_ql + hb * HD;
    const __half* k16 = g_k16 + hb * HD;
    const __half* v16 = g_v16 + hb * HD;

    const int tid = threadIdx.x;
    const int wid = tid >> 5, lane = tid & 31;
    const uint32_t lm_off = (uint32_t)(lane & 15) * RPB + (uint32_t)(lane >> 4) * 16;
    const int seg = tid & 7;
    const int rbase = tid >> 3;

#pragma unroll
    for (int t0 = 0; t0 < 2; ++t0) {
        const uint32_t ss = sKV0 + (uint32_t)(t0 * KSTG2);
        const int j0 = t0 * 64;
#pragma unroll
        for (int p = 0; p < 4; ++p) {
            const int arr = p >> 1;
            int r = (p & 1) * 32 + rbase;
            const __half* g = arr ? v16 : k16;
            cpa16(ss + (uint32_t)(arr * KTILEB + r * RPB + seg * 16),
                  g + (size_t)(j0 + r) * HD + seg * 8);
        }
        CPA_COMMIT();
    }
#pragma unroll
    for (int p = 0; p < 8; ++p) {
        const int arr = p >> 2;
        int r = (p & 3) * 32 + rbase;
        const __half* g = arr ? ql : qh;
        uint4 v = *(const uint4*)(g + (size_t)(q0 + r) * HD + seg * 8);
        *(uint4*)(smem + (arr ? TILEB : 0) + r * RPB + seg * 16) = v;
    }

    float o_[8][4];
    float mA = -INFINITY, mB = -INFINITY, lA = 0.f, lB = 0.f;
#pragma unroll
    for (int nt = 0; nt < 8; nt++)
#pragma unroll
        for (int q = 0; q < 4; q++) o_[nt][q] = 0.f;

    const int NT = NN / 64;
    for (int it = 0; it < NT; ++it) {
        if (it + 1 < NT) { CPA_WAIT1(); } else { CPA_WAIT0(); }
        __syncthreads();

        if (it + 2 < NT) {
            const int j2 = (it + 2) * 64;
            const uint32_t sst = sKV0 + (uint32_t)(((it + 2) % 3) * KSTG2);
#pragma unroll
            for (int p = 0; p < 4; ++p) {
                const int arr = p >> 1;
                int r = (p & 1) * 32 + rbase;
                const __half* g = arr ? v16 : k16;
                cpa16(sst + (uint32_t)(arr * KTILEB + r * RPB + seg * 16),
                      g + (size_t)(j2 + r) * HD + seg * 8);
            }
            CPA_COMMIT();
        }

        const uint32_t sK = sKV0 + (uint32_t)((it % 3) * KSTG2);
        const uint32_t sV = sK + KTILEB;

        // ---- S = (Qh+Ql) @ Kh^T, 2-term ----
        float s_[8][4];
#pragma unroll
        for (int nt = 0; nt < 8; nt++)
#pragma unroll
            for (int q = 0; q < 4; q++) s_[nt][q] = 0.f;

#pragma unroll
        for (int ks = 0; ks < 4; ++ks) {
            const uint32_t kso = (uint32_t)ks * 32;
            uint32_t ah[4], al[4];
            uint32_t ab = (uint32_t)(wid * 16) * RPB + kso + lm_off;
            ldm_x4(ah, sQhi + ab);
            ldm_x4(al, sQlo + ab);
            uint32_t bf[4][4];
#pragma unroll
            for (int bp = 0; bp < 4; bp++)
                ldm_x4(bf[bp], sK + (uint32_t)(16 * bp) * RPB + kso + lm_off);
#pragma unroll
            for (int bp = 0; bp < 4; bp++)
#pragma unroll
                for (int half = 0; half < 2; half++)
                    mma_f16(s_[2*bp+half], ah, bf[bp][half], bf[bp][half + 2]);
#pragma unroll
            for (int bp = 0; bp < 4; bp++)
#pragma unroll
                for (int half = 0; half < 2; half++)
                    mma_f16(s_[2*bp+half], al, bf[bp][half], bf[bp][half + 2]);
        }

        // ---- online softmax (log2 domain; Q pre-scaled) ----
        float mlA = -INFINITY, mlB = -INFINITY;
#pragma unroll
        for (int nt = 0; nt < 8; nt++) {
            mlA = fmaxf(mlA, fmaxf(s_[nt][0], s_[nt][1]));
            mlB = fmaxf(mlB, fmaxf(s_[nt][2], s_[nt][3]));
        }
#pragma unroll
        for (int off = 1; off <= 2; off <<= 1) {
            mlA = fmaxf(mlA, __shfl_xor_sync(0xffffffffu, mlA, off));
            mlB = fmaxf(mlB, __shfl_xor_sync(0xffffffffu, mlB, off));
        }
        float mnA = fmaxf(mA, mlA), mnB = fmaxf(mB, mlB);
        float aAl = ex2f(mA - mnA), aBl = ex2f(mB - mnB);
        mA = mnA; mB = mnB;
        float sumA = 0.f, sumB = 0.f;
#pragma unroll
        for (int nt = 0; nt < 8; nt++) {
            s_[nt][0] = ex2f(s_[nt][0] - mA);
            s_[nt][1] = ex2f(s_[nt][1] - mA);
            s_[nt][2] = ex2f(s_[nt][2] - mB);
            s_[nt][3] = ex2f(s_[nt][3] - mB);
            sumA += s_[nt][0] + s_[nt][1];
            sumB += s_[nt][2] + s_[nt][3];
            o_[nt][0] *= aAl; o_[nt][1] *= aAl;
            o_[nt][2] *= aBl; o_[nt][3] *= aBl;
        }
#pragma unroll
        for (int off = 1; off <= 2; off <<= 1) {
            sumA += __shfl_xor_sync(0xffffffffu, sumA, off);
            sumB += __shfl_xor_sync(0xffffffffu, sumB, off);
        }
        lA = lA * aAl + sumA;
        lB = lB * aBl + sumB;

        // ---- O += P @ V, single-term fp16 P ----
#pragma unroll
        for (int t = 0; t < 4; t++) {
            uint32_t pah[4];
#pragma unroll
            for (int i = 0; i < 4; i++) {
                const float* src = (i < 2) ? s_[2 * t] : s_[2 * t + 1];
                pah[i] = pkh2(src[(i & 1) ? 2 : 0], src[(i & 1) ? 3 : 1]);
            }
            uint32_t vf[4][4];
            const uint32_t vrow = (uint32_t)(16 * t + (lane & 7) + ((lane >> 3) & 1) * 8) * RPB
                                + (uint32_t)(lane >> 4) * 16;
#pragma unroll
            for (int db = 0; db < 4; db++)
                ldm_x4_t(vf[db], sV + vrow + (uint32_t)(32 * db));
#pragma unroll
            for (int db = 0; db < 4; db++)
#pragma unroll
                for (int half = 0; half < 2; half++)
                    mma_f16(o_[2*db+half], pah, vf[db][2*half], vf[db][2*half + 1]);
        }
    }

    // ---- epilogue ----
    const int rowA = q0 + 16 * wid + (lane >> 2);
    const int rowB = rowA + 8;
    const float invA = 1.f / lA, invB = 1.f / lB;
#pragma unroll
    for (int nt = 0; nt < 8; nt++) {
        int d0 = 8 * nt + 2 * (lane & 3);
        float2 vA = make_float2(o_[nt][0] * invA, o_[nt][1] * invA);
        float2 vB = make_float2(o_[nt][2] * invB, o_[nt][3] * invB);
        *(float2*)&out[((size_t)b * NN + rowA) * DIM + h * HD + d0] = vA;
        *(float2*)&out[((size_t)b * NN + rowB) * DIM + h * HD + d0] = vB;
    }
}

extern "C" void kernel_launch(void* const* d_in, const int* in_sizes, int n_in,
                              void* d_out, int out_size)
{
    (void)in_sizes; (void)n_in; (void)out_size;
    const float* x  = (const float*)d_in[0];
    const float* wq = (const float*)d_in[1];
    const float* bq = (const float*)d_in[2];
    const float* wk = (const float*)d_in[3];
    const float* bk = (const float*)d_in[4];
    const float* wv = (const float*)d_in[5];
    const float* bv = (const float*)d_in[6];
    float* out = (float*)d_out;

    {
        __half *xh, *xl, *wq16, *wk16, *wv16;
        cudaGetSymbolAddress((void**)&xh, g_xh);
        cudaGetSymbolAddress((void**)&xl, g_xl);
        cudaGetSymbolAddress((void**)&wq16, g_wq16);
        cudaGetSymbolAddress((void**)&wk16, g_wk16);
        cudaGetSymbolAddress((void**)&wv16, g_wv16);
        int n4x = MROWS * DIM / 4;
        split_x<<<(n4x + 255) / 256, 256>>>((const float4*)x, (uint2*)xh, (uint2*)xl, n4x);
        int n4w = DIM * DIM / 4;
        cvt_w<<<(n4w + 255) / 256, 256>>>((const float4*)wq, (uint2*)wq16, n4w);
        cvt_w<<<(n4w + 255) / 256, 256>>>((const float4*)wk, (uint2*)wk16, n4w);
        cvt_w<<<(n4w + 255) / 256, 256>>>((const float4*)wv, (uint2*)wv16, n4w);
    }

    size_t q_smem = 3 * (size_t)QSTG3;   // 92160 B
    cudaFuncSetAttribute(qkv_mma, cudaFuncAttributeMaxDynamicSharedMemorySize,
                         (int)q_smem);
    dim3 g1(DIM / 128, MROWS / 128, 3);
    qkv_mma<<<g1, 256, q_smem>>>(bq, bk, bv);

    size_t a_smem = 2 * (size_t)TILEB + 3 * (size_t)KSTG2;   // 92160 B
    cudaFuncSetAttribute(attn_mma, cudaFuncAttributeMaxDynamicSharedMemorySize,
                         (int)a_smem);
    dim3 g2(NN / 128, NH, BB);
    attn_mma<<<g2, 256, a_smem>>>(out);
}

// round 16
// speedup vs baseline: 1.7937x; 1.1167x over previous
#include <cuda_runtime.h>
#include <cuda_fp16.h>
#include <math.h>
#include <stdint.h>

#define BB 4
#define NN 2048
#define DIM 768
#define NH 12
#define HD 64
#define MROWS (BB*NN)   // 8192
#define SZT (BB*NH*NN*HD)

// scratch: Q split hi/lo fp16; K,V single fp16; [b,h,n,d] layout
__device__ __align__(16) __half g_qh[SZT], g_ql[SZT];
__device__ __align__(16) __half g_k16[SZT];
__device__ __align__(16) __half g_v16[SZT];
// pre-converted inputs: x split hi/lo, weights single fp16
__device__ __align__(16) __half g_xh[MROWS*DIM], g_xl[MROWS*DIM];
__device__ __align__(16) __half g_wq16[DIM*DIM], g_wk16[DIM*DIM], g_wv16[DIM*DIM];

// ====================== helpers ======================
__device__ __forceinline__ uint32_t smem_u32(const void* p) {
    uint32_t a;
    asm("{ .reg .u64 t; cvta.to.shared.u64 t, %1; cvt.u32.u64 %0, t; }"
        : "=r"(a) : "l"(p));
    return a;
}
__device__ __forceinline__ void ldm_x4(uint32_t* r, uint32_t addr) {
    asm volatile("ldmatrix.sync.aligned.m8n8.x4.shared.b16 {%0,%1,%2,%3}, [%4];"
                 : "=r"(r[0]), "=r"(r[1]), "=r"(r[2]), "=r"(r[3]) : "r"(addr));
}
__device__ __forceinline__ void ldm_x4_t(uint32_t* r, uint32_t addr) {
    asm volatile("ldmatrix.sync.aligned.m8n8.x4.trans.shared.b16 {%0,%1,%2,%3}, [%4];"
                 : "=r"(r[0]), "=r"(r[1]), "=r"(r[2]), "=r"(r[3]) : "r"(addr));
}
__device__ __forceinline__ void mma_f16(float* c, const uint32_t* a,
                                        uint32_t b0, uint32_t b1) {
    asm volatile(
        "mma.sync.aligned.m16n8k16.row.col.f32.f16.f16.f32 "
        "{%0,%1,%2,%3}, {%4,%5,%6,%7}, {%8,%9}, {%0,%1,%2,%3};"
        : "+f"(c[0]), "+f"(c[1]), "+f"(c[2]), "+f"(c[3])
        : "r"(a[0]), "r"(a[1]), "r"(a[2]), "r"(a[3]), "r"(b0), "r"(b1));
}
__device__ __forceinline__ float ex2f(float x) {
    float y;
    asm("ex2.approx.ftz.f32 %0, %1;" : "=f"(y) : "f"(x));
    return y;
}
// fp16 split: h = rn(x), l = exact remainder (|l| <= 2^-12 |x|)
__device__ __forceinline__ void split2h(float x0, float x1, uint32_t& h, uint32_t& l) {
    __half2 hh = __floats2half2_rn(x0, x1);
    float2 hf = __half22float2(hh);
    __half2 ll = __floats2half2_rn(x0 - hf.x, x1 - hf.y);
    h = *(uint32_t*)&hh;
    l = *(uint32_t*)&ll;
}
__device__ __forceinline__ uint32_t pkh2(float x0, float x1) {
    __half2 hh = __floats2half2_rn(x0, x1);
    return *(uint32_t*)&hh;
}
__device__ __forceinline__ void cpa16(uint32_t s, const void* g) {
    asm volatile("cp.async.cg.shared.global [%0], [%1], 16;"
                 :: "r"(s), "l"(g) : "memory");
}
#define CPA_COMMIT() asm volatile("cp.async.commit_group;" ::: "memory")
#define CPA_WAIT0()  asm volatile("cp.async.wait_group 0;" ::: "memory")
#define CPA_WAIT1()  asm volatile("cp.async.wait_group 1;" ::: "memory")

#define RPB 144
#define TILEB (128*RPB)           // 18432 B
#define KTILEB (64*RPB)           // 9216 B
#define KSTG2 (2*KTILEB)          // K + V per stage

// ===================== input conversion =====================
__global__ __launch_bounds__(256) void split_x(
    const float4* __restrict__ src, uint2* __restrict__ dh,
    uint2* __restrict__ dl, int n4)
{
    int i = blockIdx.x * 256 + threadIdx.x;
    if (i >= n4) return;
    float4 v = src[i];
    uint32_t h0, l0, h1, l1;
    split2h(v.x, v.y, h0, l0);
    split2h(v.z, v.w, h1, l1);
    dh[i] = make_uint2(h0, h1);
    dl[i] = make_uint2(l0, l1);
}
__global__ __launch_bounds__(256) void cvt_w(
    const float4* __restrict__ src, uint2* __restrict__ dst, int n4)
{
    int i = blockIdx.x * 256 + threadIdx.x;
    if (i >= n4) return;
    float4 v = src[i];
    dst[i] = make_uint2(pkh2(v.x, v.y), pkh2(v.z, v.w));
}

// ===================== QKV GEMM: fp16, 3-stage cp.async =====================
// Q (mat=0): 2-term (x hi/lo); K,V (mat=1,2): single-term x.
#define QCH 32
#define QROWB 80
#define QTILE (128*QROWB)         // 10240 B
#define QSTG3 (3*QTILE)

__global__ __launch_bounds__(256, 2) void qkv_mma(
    const float* __restrict__ bq, const float* __restrict__ bk,
    const float* __restrict__ bv)
{
    extern __shared__ char smem[];
    const uint32_t sbase = smem_u32(smem);

    const int mat = blockIdx.z;
    const __half* w16 = (mat == 0) ? g_wq16 : (mat == 1) ? g_wk16 : g_wv16;
    const float* bias = (mat == 0) ? bq : (mat == 1) ? bk : bv;
    __half* dh = (mat == 0) ? g_qh : (mat == 1) ? g_k16 : g_v16;
    const float osc = (mat == 0) ? 0.125f * 1.44269504f : 1.0f;
    const bool twoTerm = (mat == 0);

    const int m0 = blockIdx.y * 128;
    const int o0 = blockIdx.x * 128;
    const int tid = threadIdx.x;
    const int wid = tid >> 5, lane = tid & 31;
    const int warpM = wid & 3, warpN = wid >> 2;
    const int m0w = warpM * 32, n0w = warpN * 64;
    const uint32_t lm_off = (uint32_t)(lane & 15) * QROWB + (uint32_t)(lane >> 4) * 16;
    const int lrow = tid >> 2, lseg = tid & 3;

    float acc[2][8][4];
#pragma unroll
    for (int mt = 0; mt < 2; mt++)
#pragma unroll
        for (int nt = 0; nt < 8; nt++)
#pragma unroll
            for (int q = 0; q < 4; q++) acc[mt][nt][q] = 0.f;

    const int NC = DIM / QCH;   // 24
    const int npf = twoTerm ? 6 : 4;   // cp.async float4s per thread per chunk

#pragma unroll
    for (int c0 = 0; c0 < 2; ++c0) {
        const uint32_t ss = sbase + (uint32_t)(c0 * QSTG3);
        const int kb = c0 * QCH;
        for (int p = 0; p < npf; ++p) {
            // arrays: 0=xh, 1=w, 2=xl  (so single-term path uses 0,1 only)
            int arr = p >> 1;
            int row = (p & 1) * 64 + lrow;
            const __half* g =
                (arr == 0) ? g_xh + (size_t)(m0 + row) * DIM :
                (arr == 1) ? w16 + (size_t)(o0 + row) * DIM :
                             g_xl + (size_t)(m0 + row) * DIM;
            cpa16(ss + (uint32_t)(arr * QTILE + row * QROWB + lseg * 16),
                  g + kb + lseg * 8);
        }
        CPA_COMMIT();
    }

    for (int c = 0; c < NC; ++c) {
        if (c + 1 < NC) { CPA_WAIT1(); } else { CPA_WAIT0(); }
        __syncthreads();

        if (c + 2 < NC) {
            const int kb = (c + 2) * QCH;
            const uint32_t ss = sbase + (uint32_t)(((c + 2) % 3) * QSTG3);
            for (int p = 0; p < npf; ++p) {
                int arr = p >> 1;
                int row = (p & 1) * 64 + lrow;
                const __half* g =
                    (arr == 0) ? g_xh + (size_t)(m0 + row) * DIM :
                    (arr == 1) ? w16 + (size_t)(o0 + row) * DIM :
                                 g_xl + (size_t)(m0 + row) * DIM;
                cpa16(ss + (uint32_t)(arr * QTILE + row * QROWB + lseg * 16),
                      g + kb + lseg * 8);
            }
            CPA_COMMIT();
        }

        const uint32_t sAh = sbase + (uint32_t)((c % 3) * QSTG3);
        const uint32_t sBh = sAh + QTILE;
        const uint32_t sAl = sBh + QTILE;

#pragma unroll
        for (int ks = 0; ks < 2; ++ks) {
            const uint32_t kso = (uint32_t)ks * 32;
            uint32_t a_hi[2][4];
#pragma unroll
            for (int mt = 0; mt < 2; mt++)
                ldm_x4(a_hi[mt], sAh + (uint32_t)(m0w + 16 * mt) * QROWB + kso + lm_off);
            uint32_t bf[4][4];
#pragma unroll
            for (int bp = 0; bp < 4; bp++)
                ldm_x4(bf[bp], sBh + (uint32_t)(n0w + 16 * bp) * QROWB + kso + lm_off);
#pragma unroll
            for (int bp = 0; bp < 4; bp++)
#pragma unroll
                for (int half = 0; half < 2; half++)
#pragma unroll
                    for (int mt = 0; mt < 2; mt++)
                        mma_f16(acc[mt][2*bp+half], a_hi[mt], bf[bp][half], bf[bp][half + 2]);
            if (twoTerm) {
                uint32_t a_lo[2][4];
#pragma unroll
                for (int mt = 0; mt < 2; mt++)
                    ldm_x4(a_lo[mt], sAl + (uint32_t)(m0w + 16 * mt) * QROWB + kso + lm_off);
#pragma unroll
                for (int bp = 0; bp < 4; bp++)
#pragma unroll
                    for (int half = 0; half < 2; half++)
#pragma unroll
                        for (int mt = 0; mt < 2; mt++)
                            mma_f16(acc[mt][2*bp+half], a_lo[mt], bf[bp][half], bf[bp][half + 2]);
            }
        }
    }

#pragma unroll
    for (int mt = 0; mt < 2; mt++) {
#pragma unroll
        for (int nt = 0; nt < 8; nt++) {
            int row0 = m0 + m0w + 16 * mt + (lane >> 2);
            int col  = o0 + n0w + 8 * nt + 2 * (lane & 3);
            int h = col / HD, d = col & (HD - 1);
            float b0 = bias[col], b1 = bias[col + 1];
#pragma unroll
            for (int half = 0; half < 2; half++) {
                int row = row0 + 8 * half;
                int b_ = row >> 11, n = row & (NN - 1);
                size_t idx = (((size_t)b_ * NH + h) * NN + n) * HD + d;
                float y0 = (acc[mt][nt][2*half]     + b0) * osc;
                float y1 = (acc[mt][nt][2*half + 1] + b1) * osc;
                __half2 hp = __floats2half2_rn(y0, y1);
                *(uint32_t*)(dh + idx) = *(uint32_t*)&hp;
                if (mat == 0) {
                    float2 hf = __half22float2(hp);
                    __half2 lp = __floats2half2_rn(y0 - hf.x, y1 - hf.y);
                    *(uint32_t*)(g_ql + idx) = *(uint32_t*)&lp;
                }
            }
        }
    }
}

// ===================== Flash attention: fp16, single-term P@V =====================
__global__ __launch_bounds__(256, 2) void attn_mma(float* __restrict__ out)
{
    extern __shared__ char smem[];
    const uint32_t sbase = smem_u32(smem);
    const uint32_t sQhi = sbase;
    const uint32_t sQlo = sbase + TILEB;
    const uint32_t sKV0 = sbase + 2 * TILEB;

    const int b = blockIdx.z, h = blockIdx.y;
    const int q0 = blockIdx.x * 128;
    const size_t hb = ((size_t)b * NH + h) * NN;
    const __half* qh = g_qh + hb * HD;
    const __half* ql = g_ql + hb * HD;
    const __half* k16 = g_k16 + hb * HD;
    const __half* v16 = g_v16 + hb * HD;

    const int tid = threadIdx.x;
    const int wid = tid >> 5, lane = tid & 31;
    const uint32_t lm_off = (uint32_t)(lane & 15) * RPB + (uint32_t)(lane >> 4) * 16;
    const int seg = tid & 7;
    const int rbase = tid >> 3;

#pragma unroll
    for (int t0 = 0; t0 < 2; ++t0) {
        const uint32_t ss = sKV0 + (uint32_t)(t0 * KSTG2);
        const int j0 = t0 * 64;
#pragma unroll
        for (int p = 0; p < 4; ++p) {
            const int arr = p >> 1;
            int r = (p & 1) * 32 + rbase;
            const __half* g = arr ? v16 : k16;
            cpa16(ss + (uint32_t)(arr * KTILEB + r * RPB + seg * 16),
                  g + (size_t)(j0 + r) * HD + seg * 8);
        }
        CPA_COMMIT();
    }
#pragma unroll
    for (int p = 0; p < 8; ++p) {
        const int arr = p >> 2;
        int r = (p & 3) * 32 + rbase;
        const __half* g = arr ? ql : qh;
        uint4 v = *(const uint4*)(g + (size_t)(q0 + r) * HD + seg * 8);
        *(uint4*)(smem + (arr ? TILEB : 0) + r * RPB + seg * 16) = v;
    }

    float o_[8][4];
    float mA = -INFINITY, mB = -INFINITY, lA = 0.f, lB = 0.f;
#pragma unroll
    for (int nt = 0; nt < 8; nt++)
#pragma unroll
        for (int q = 0; q < 4; q++) o_[nt][q] = 0.f;

    const int NT = NN / 64;
    for (int it = 0; it < NT; ++it) {
        if (it + 1 < NT) { CPA_WAIT1(); } else { CPA_WAIT0(); }
        __syncthreads();

        if (it + 2 < NT) {
            const int j2 = (it + 2) * 64;
            const uint32_t sst = sKV0 + (uint32_t)(((it + 2) % 3) * KSTG2);
#pragma unroll
            for (int p = 0; p < 4; ++p) {
                const int arr = p >> 1;
                int r = (p & 1) * 32 + rbase;
                const __half* g = arr ? v16 : k16;
                cpa16(sst + (uint32_t)(arr * KTILEB + r * RPB + seg * 16),
                      g + (size_t)(j2 + r) * HD + seg * 8);
            }
            CPA_COMMIT();
        }

        const uint32_t sK = sKV0 + (uint32_t)((it % 3) * KSTG2);
        const uint32_t sV = sK + KTILEB;

        // ---- S = (Qh+Ql) @ Kh^T, 2-term ----
        float s_[8][4];
#pragma unroll
        for (int nt = 0; nt < 8; nt++)
#pragma unroll
            for (int q = 0; q < 4; q++) s_[nt][q] = 0.f;

#pragma unroll
        for (int ks = 0; ks < 4; ++ks) {
            const uint32_t kso = (uint32_t)ks * 32;
            uint32_t ah[4], al[4];
            uint32_t ab = (uint32_t)(wid * 16) * RPB + kso + lm_off;
            ldm_x4(ah, sQhi + ab);
            ldm_x4(al, sQlo + ab);
            uint32_t bf[4][4];
#pragma unroll
            for (int bp = 0; bp < 4; bp++)
                ldm_x4(bf[bp], sK + (uint32_t)(16 * bp) * RPB + kso + lm_off);
#pragma unroll
            for (int bp = 0; bp < 4; bp++)
#pragma unroll
                for (int half = 0; half < 2; half++)
                    mma_f16(s_[2*bp+half], ah, bf[bp][half], bf[bp][half + 2]);
#pragma unroll
            for (int bp = 0; bp < 4; bp++)
#pragma unroll
                for (int half = 0; half < 2; half++)
                    mma_f16(s_[2*bp+half], al, bf[bp][half], bf[bp][half + 2]);
        }

        // ---- online softmax (log2 domain; Q pre-scaled) ----
        float mlA = -INFINITY, mlB = -INFINITY;
#pragma unroll
        for (int nt = 0; nt < 8; nt++) {
            mlA = fmaxf(mlA, fmaxf(s_[nt][0], s_[nt][1]));
            mlB = fmaxf(mlB, fmaxf(s_[nt][2], s_[nt][3]));
        }
#pragma unroll
        for (int off = 1; off <= 2; off <<= 1) {
            mlA = fmaxf(mlA, __shfl_xor_sync(0xffffffffu, mlA, off));
            mlB = fmaxf(mlB, __shfl_xor_sync(0xffffffffu, mlB, off));
        }
        float mnA = fmaxf(mA, mlA), mnB = fmaxf(mB, mlB);
        float aAl = ex2f(mA - mnA), aBl = ex2f(mB - mnB);
        mA = mnA; mB = mnB;
        float sumA = 0.f, sumB = 0.f;
#pragma unroll
        for (int nt = 0; nt < 8; nt++) {
            s_[nt][0] = ex2f(s_[nt][0] - mA);
            s_[nt][1] = ex2f(s_[nt][1] - mA);
            s_[nt][2] = ex2f(s_[nt][2] - mB);
            s_[nt][3] = ex2f(s_[nt][3] - mB);
            sumA += s_[nt][0] + s_[nt][1];
            sumB += s_[nt][2] + s_[nt][3];
            o_[nt][0] *= aAl; o_[nt][1] *= aAl;
            o_[nt][2] *= aBl; o_[nt][3] *= aBl;
        }
#pragma unroll
        for (int off = 1; off <= 2; off <<= 1) {
            sumA += __shfl_xor_sync(0xffffffffu, sumA, off);
            sumB += __shfl_xor_sync(0xffffffffu, sumB, off);
        }
        lA = lA * aAl + sumA;
        lB = lB * aBl + sumB;

        // ---- O += P @ V, single-term fp16 P ----
#pragma unroll
        for (int t = 0; t < 4; t++) {
            uint32_t pah[4];
#pragma unroll
            for (int i = 0; i < 4; i++) {
                const float* src = (i < 2) ? s_[2 * t] : s_[2 * t + 1];
                pah[i] = pkh2(src[(i & 1) ? 2 : 0], src[(i & 1) ? 3 : 1]);
            }
            uint32_t vf[4][4];
            const uint32_t vrow = (uint32_t)(16 * t + (lane & 7) + ((lane >> 3) & 1) * 8) * RPB
                                + (uint32_t)(lane >> 4) * 16;
#pragma unroll
            for (int db = 0; db < 4; db++)
                ldm_x4_t(vf[db], sV + vrow + (uint32_t)(32 * db));
#pragma unroll
            for (int db = 0; db < 4; db++)
#pragma unroll
                for (int half = 0; half < 2; half++)
                    mma_f16(o_[2*db+half], pah, vf[db][2*half], vf[db][2*half + 1]);
        }
    }

    // ---- epilogue ----
    const int rowA = q0 + 16 * wid + (lane >> 2);
    const int rowB = rowA + 8;
    const float invA = 1.f / lA, invB = 1.f / lB;
#pragma unroll
    for (int nt = 0; nt < 8; nt++) {
        int d0 = 8 * nt + 2 * (lane & 3);
        float2 vA = make_float2(o_[nt][0] * invA, o_[nt][1] * invA);
        float2 vB = make_float2(o_[nt][2] * invB, o_[nt][3] * invB);
        *(float2*)&out[((size_t)b * NN + rowA) * DIM + h * HD + d0] = vA;
        *(float2*)&out[((size_t)b * NN + rowB) * DIM + h * HD + d0] = vB;
    }
}

extern "C" void kernel_launch(void* const* d_in, const int* in_sizes, int n_in,
                              void* d_out, int out_size)
{
    (void)in_sizes; (void)n_in; (void)out_size;
    const float* x  = (const float*)d_in[0];
    const float* wq = (const float*)d_in[1];
    const float* bq = (const float*)d_in[2];
    const float* wk = (const float*)d_in[3];
    const float* bk = (const float*)d_in[4];
    const float* wv = (const float*)d_in[5];
    const float* bv = (const float*)d_in[6];
    float* out = (float*)d_out;

    {
        __half *xh, *xl, *wq16, *wk16, *wv16;
        cudaGetSymbolAddress((void**)&xh, g_xh);
        cudaGetSymbolAddress((void**)&xl, g_xl);
        cudaGetSymbolAddress((void**)&wq16, g_wq16);
        cudaGetSymbolAddress((void**)&wk16, g_wk16);
        cudaGetSymbolAddress((void**)&wv16, g_wv16);
        int n4x = MROWS * DIM / 4;
        split_x<<<(n4x + 255) / 256, 256>>>((const float4*)x, (uint2*)xh, (uint2*)xl, n4x);
        int n4w = DIM * DIM / 4;
        cvt_w<<<(n4w + 255) / 256, 256>>>((const float4*)wq, (uint2*)wq16, n4w);
        cvt_w<<<(n4w + 255) / 256, 256>>>((const float4*)wk, (uint2*)wk16, n4w);
        cvt_w<<<(n4w + 255) / 256, 256>>>((const float4*)wv, (uint2*)wv16, n4w);
    }

    size_t q_smem = 3 * (size_t)QSTG3;   // 92160 B
    cudaFuncSetAttribute(qkv_mma, cudaFuncAttributeMaxDynamicSharedMemorySize,
                         (int)q_smem);
    dim3 g1(DIM / 128, MROWS / 128, 3);
    qkv_mma<<<g1, 256, q_smem>>>(bq, bk, bv);

    size_t a_smem = 2 * (size_t)TILEB + 3 * (size_t)KSTG2;   // 92160 B
    cudaFuncSetAttribute(attn_mma, cudaFuncAttributeMaxDynamicSharedMemorySize,
                         (int)a_smem);
    dim3 g2(NN / 128, NH, BB);
    attn_mma<<<g2, 256, a_smem>>>(out);
}

// round 17
// speedup vs baseline: 2.0874x; 1.1637x over previous
#include <cuda_runtime.h>
#include <cuda_fp16.h>
#include <math.h>
#include <stdint.h>

#define BB 4
#define NN 2048
#define DIM 768
#define NH 12
#define HD 64
#define MROWS (BB*NN)   // 8192
#define SZT (BB*NH*NN*HD)

// scratch: q,k,v single fp16, [b,h,n,d] layout
__device__ __align__(16) __half g_q16[SZT];
__device__ __align__(16) __half g_k16[SZT];
__device__ __align__(16) __half g_v16[SZT];
// pre-converted inputs: x split hi/lo (for accurate Q projection), weights single fp16
__device__ __align__(16) __half g_xh[MROWS*DIM], g_xl[MROWS*DIM];
__device__ __align__(16) __half g_wq16[DIM*DIM], g_wk16[DIM*DIM], g_wv16[DIM*DIM];

// ====================== helpers ======================
__device__ __forceinline__ uint32_t smem_u32(const void* p) {
    uint32_t a;
    asm("{ .reg .u64 t; cvta.to.shared.u64 t, %1; cvt.u32.u64 %0, t; }"
        : "=r"(a) : "l"(p));
    return a;
}
__device__ __forceinline__ void ldm_x4(uint32_t* r, uint32_t addr) {
    asm volatile("ldmatrix.sync.aligned.m8n8.x4.shared.b16 {%0,%1,%2,%3}, [%4];"
                 : "=r"(r[0]), "=r"(r[1]), "=r"(r[2]), "=r"(r[3]) : "r"(addr));
}
__device__ __forceinline__ void ldm_x4_t(uint32_t* r, uint32_t addr) {
    asm volatile("ldmatrix.sync.aligned.m8n8.x4.trans.shared.b16 {%0,%1,%2,%3}, [%4];"
                 : "=r"(r[0]), "=r"(r[1]), "=r"(r[2]), "=r"(r[3]) : "r"(addr));
}
__device__ __forceinline__ void mma_f16(float* c, const uint32_t* a,
                                        uint32_t b0, uint32_t b1) {
    asm volatile(
        "mma.sync.aligned.m16n8k16.row.col.f32.f16.f16.f32 "
        "{%0,%1,%2,%3}, {%4,%5,%6,%7}, {%8,%9}, {%0,%1,%2,%3};"
        : "+f"(c[0]), "+f"(c[1]), "+f"(c[2]), "+f"(c[3])
        : "r"(a[0]), "r"(a[1]), "r"(a[2]), "r"(a[3]), "r"(b0), "r"(b1));
}
__device__ __forceinline__ float ex2f(float x) {
    float y;
    asm("ex2.approx.ftz.f32 %0, %1;" : "=f"(y) : "f"(x));
    return y;
}
// fp16 split: h = rn(x), l = exact remainder
__device__ __forceinline__ void split2h(float x0, float x1, uint32_t& h, uint32_t& l) {
    __half2 hh = __floats2half2_rn(x0, x1);
    float2 hf = __half22float2(hh);
    __half2 ll = __floats2half2_rn(x0 - hf.x, x1 - hf.y);
    h = *(uint32_t*)&hh;
    l = *(uint32_t*)&ll;
}
__device__ __forceinline__ uint32_t pkh2(float x0, float x1) {
    __half2 hh = __floats2half2_rn(x0, x1);
    return *(uint32_t*)&hh;
}
__device__ __forceinline__ void cpa16(uint32_t s, const void* g) {
    asm volatile("cp.async.cg.shared.global [%0], [%1], 16;"
                 :: "r"(s), "l"(g) : "memory");
}
#define CPA_COMMIT() asm volatile("cp.async.commit_group;" ::: "memory")
#define CPA_WAIT0()  asm volatile("cp.async.wait_group 0;" ::: "memory")
#define CPA_WAIT1()  asm volatile("cp.async.wait_group 1;" ::: "memory")

#define RPB 144
#define TILEB (128*RPB)           // 18432 B
#define KTILEB (64*RPB)           // 9216 B
#define KSTG2 (2*KTILEB)          // K + V per stage

// ===================== input conversion =====================
__global__ __launch_bounds__(256) void split_x(
    const float4* __restrict__ src, uint2* __restrict__ dh,
    uint2* __restrict__ dl, int n4)
{
    int i = blockIdx.x * 256 + threadIdx.x;
    if (i >= n4) return;
    float4 v = src[i];
    uint32_t h0, l0, h1, l1;
    split2h(v.x, v.y, h0, l0);
    split2h(v.z, v.w, h1, l1);
    dh[i] = make_uint2(h0, h1);
    dl[i] = make_uint2(l0, l1);
}
// all three weight matrices in one launch (blockIdx.z selects)
__global__ __launch_bounds__(256) void cvt_w3(
    const float4* __restrict__ wq, const float4* __restrict__ wk,
    const float4* __restrict__ wv,
    uint2* __restrict__ dq, uint2* __restrict__ dk, uint2* __restrict__ dv,
    int n4)
{
    int i = blockIdx.x * 256 + threadIdx.x;
    if (i >= n4) return;
    const float4* src = (blockIdx.z == 0) ? wq : (blockIdx.z == 1) ? wk : wv;
    uint2* dst        = (blockIdx.z == 0) ? dq : (blockIdx.z == 1) ? dk : dv;
    float4 v = src[i];
    dst[i] = make_uint2(pkh2(v.x, v.y), pkh2(v.z, v.w));
}

// ===================== QKV GEMM: fp16, 3-stage cp.async =====================
// Q (mat=0): 2-term (x hi/lo) for well-rounded qh; K,V: single-term x.
#define QCH 32
#define QROWB 80
#define QTILE (128*QROWB)         // 10240 B
#define QSTG3 (3*QTILE)

__global__ __launch_bounds__(256, 2) void qkv_mma(
    const float* __restrict__ bq, const float* __restrict__ bk,
    const float* __restrict__ bv)
{
    extern __shared__ char smem[];
    const uint32_t sbase = smem_u32(smem);

    const int mat = blockIdx.z;
    const __half* w16 = (mat == 0) ? g_wq16 : (mat == 1) ? g_wk16 : g_wv16;
    const float* bias = (mat == 0) ? bq : (mat == 1) ? bk : bv;
    __half* dh = (mat == 0) ? g_q16 : (mat == 1) ? g_k16 : g_v16;
    const float osc = (mat == 0) ? 0.125f * 1.44269504f : 1.0f;
    const bool twoTerm = (mat == 0);

    const int m0 = blockIdx.y * 128;
    const int o0 = blockIdx.x * 128;
    const int tid = threadIdx.x;
    const int wid = tid >> 5, lane = tid & 31;
    const int warpM = wid & 3, warpN = wid >> 2;
    const int m0w = warpM * 32, n0w = warpN * 64;
    const uint32_t lm_off = (uint32_t)(lane & 15) * QROWB + (uint32_t)(lane >> 4) * 16;
    const int lrow = tid >> 2, lseg = tid & 3;

    float acc[2][8][4];
#pragma unroll
    for (int mt = 0; mt < 2; mt++)
#pragma unroll
        for (int nt = 0; nt < 8; nt++)
#pragma unroll
            for (int q = 0; q < 4; q++) acc[mt][nt][q] = 0.f;

    const int NC = DIM / QCH;   // 24
    const int npf = twoTerm ? 6 : 4;

#pragma unroll
    for (int c0 = 0; c0 < 2; ++c0) {
        const uint32_t ss = sbase + (uint32_t)(c0 * QSTG3);
        const int kb = c0 * QCH;
        for (int p = 0; p < npf; ++p) {
            int arr = p >> 1;   // 0=xh, 1=w, 2=xl
            int row = (p & 1) * 64 + lrow;
            const __half* g =
                (arr == 0) ? g_xh + (size_t)(m0 + row) * DIM :
                (arr == 1) ? w16 + (size_t)(o0 + row) * DIM :
                             g_xl + (size_t)(m0 + row) * DIM;
            cpa16(ss + (uint32_t)(arr * QTILE + row * QROWB + lseg * 16),
                  g + kb + lseg * 8);
        }
        CPA_COMMIT();
    }

    for (int c = 0; c < NC; ++c) {
        if (c + 1 < NC) { CPA_WAIT1(); } else { CPA_WAIT0(); }
        __syncthreads();

        if (c + 2 < NC) {
            const int kb = (c + 2) * QCH;
            const uint32_t ss = sbase + (uint32_t)(((c + 2) % 3) * QSTG3);
            for (int p = 0; p < npf; ++p) {
                int arr = p >> 1;
                int row = (p & 1) * 64 + lrow;
                const __half* g =
                    (arr == 0) ? g_xh + (size_t)(m0 + row) * DIM :
                    (arr == 1) ? w16 + (size_t)(o0 + row) * DIM :
                                 g_xl + (size_t)(m0 + row) * DIM;
                cpa16(ss + (uint32_t)(arr * QTILE + row * QROWB + lseg * 16),
                      g + kb + lseg * 8);
            }
            CPA_COMMIT();
        }

        const uint32_t sAh = sbase + (uint32_t)((c % 3) * QSTG3);
        const uint32_t sBh = sAh + QTILE;
        const uint32_t sAl = sBh + QTILE;

#pragma unroll
        for (int ks = 0; ks < 2; ++ks) {
            const uint32_t kso = (uint32_t)ks * 32;
            uint32_t a_hi[2][4];
#pragma unroll
            for (int mt = 0; mt < 2; mt++)
                ldm_x4(a_hi[mt], sAh + (uint32_t)(m0w + 16 * mt) * QROWB + kso + lm_off);
            uint32_t bf[4][4];
#pragma unroll
            for (int bp = 0; bp < 4; bp++)
                ldm_x4(bf[bp], sBh + (uint32_t)(n0w + 16 * bp) * QROWB + kso + lm_off);
#pragma unroll
            for (int bp = 0; bp < 4; bp++)
#pragma unroll
                for (int half = 0; half < 2; half++)
#pragma unroll
                    for (int mt = 0; mt < 2; mt++)
                        mma_f16(acc[mt][2*bp+half], a_hi[mt], bf[bp][half], bf[bp][half + 2]);
            if (twoTerm) {
                uint32_t a_lo[2][4];
#pragma unroll
                for (int mt = 0; mt < 2; mt++)
                    ldm_x4(a_lo[mt], sAl + (uint32_t)(m0w + 16 * mt) * QROWB + kso + lm_off);
#pragma unroll
                for (int bp = 0; bp < 4; bp++)
#pragma unroll
                    for (int half = 0; half < 2; half++)
#pragma unroll
                        for (int mt = 0; mt < 2; mt++)
                            mma_f16(acc[mt][2*bp+half], a_lo[mt], bf[bp][half], bf[bp][half + 2]);
            }
        }
    }

#pragma unroll
    for (int mt = 0; mt < 2; mt++) {
#pragma unroll
        for (int nt = 0; nt < 8; nt++) {
            int row0 = m0 + m0w + 16 * mt + (lane >> 2);
            int col  = o0 + n0w + 8 * nt + 2 * (lane & 3);
            int h = col / HD, d = col & (HD - 1);
            float b0 = bias[col], b1 = bias[col + 1];
#pragma unroll
            for (int half = 0; half < 2; half++) {
                int row = row0 + 8 * half;
                int b_ = row >> 11, n = row & (NN - 1);
                size_t idx = (((size_t)b_ * NH + h) * NN + n) * HD + d;
                float y0 = (acc[mt][nt][2*half]     + b0) * osc;
                float y1 = (acc[mt][nt][2*half + 1] + b1) * osc;
                *(uint32_t*)(dh + idx) = pkh2(y0, y1);
            }
        }
    }
}

// ===================== Flash attention: all-fp16 single-term =====================
__global__ __launch_bounds__(256, 2) void attn_mma(float* __restrict__ out)
{
    extern __shared__ char smem[];
    const uint32_t sbase = smem_u32(smem);
    const uint32_t sQ = sbase;
    const uint32_t sKV0 = sbase + TILEB;

    const int b = blockIdx.z, h = blockIdx.y;
    const int q0 = blockIdx.x * 128;
    const size_t hb = ((size_t)b * NH + h) * NN;
    const __half* q16 = g_q16 + hb * HD;
    const __half* k16 = g_k16 + hb * HD;
    const __half* v16 = g_v16 + hb * HD;

    const int tid = threadIdx.x;
    const int wid = tid >> 5, lane = tid & 31;
    const uint32_t lm_off = (uint32_t)(lane & 15) * RPB + (uint32_t)(lane >> 4) * 16;
    const int seg = tid & 7;
    const int rbase = tid >> 3;

#pragma unroll
    for (int t0 = 0; t0 < 2; ++t0) {
        const uint32_t ss = sKV0 + (uint32_t)(t0 * KSTG2);
        const int j0 = t0 * 64;
#pragma unroll
        for (int p = 0; p < 4; ++p) {
            const int arr = p >> 1;
            int r = (p & 1) * 32 + rbase;
            const __half* g = arr ? v16 : k16;
            cpa16(ss + (uint32_t)(arr * KTILEB + r * RPB + seg * 16),
                  g + (size_t)(j0 + r) * HD + seg * 8);
        }
        CPA_COMMIT();
    }
    // copy Q (single fp16, pre-scaled): 128 rows x 8 segs = 4 float4/thread
#pragma unroll
    for (int p = 0; p < 4; ++p) {
        int r = p * 32 + rbase;
        uint4 v = *(const uint4*)(q16 + (size_t)(q0 + r) * HD + seg * 8);
        *(uint4*)(smem + r * RPB + seg * 16) = v;
    }

    float o_[8][4];
    float mA = -INFINITY, mB = -INFINITY, lA = 0.f, lB = 0.f;
#pragma unroll
    for (int nt = 0; nt < 8; nt++)
#pragma unroll
        for (int q = 0; q < 4; q++) o_[nt][q] = 0.f;

    const int NT = NN / 64;
    for (int it = 0; it < NT; ++it) {
        if (it + 1 < NT) { CPA_WAIT1(); } else { CPA_WAIT0(); }
        __syncthreads();

        if (it + 2 < NT) {
            const int j2 = (it + 2) * 64;
            const uint32_t sst = sKV0 + (uint32_t)(((it + 2) % 3) * KSTG2);
#pragma unroll
            for (int p = 0; p < 4; ++p) {
                const int arr = p >> 1;
                int r = (p & 1) * 32 + rbase;
                const __half* g = arr ? v16 : k16;
                cpa16(sst + (uint32_t)(arr * KTILEB + r * RPB + seg * 16),
                      g + (size_t)(j2 + r) * HD + seg * 8);
            }
            CPA_COMMIT();
        }

        const uint32_t sK = sKV0 + (uint32_t)((it % 3) * KSTG2);
        const uint32_t sV = sK + KTILEB;

        // ---- S = Q @ K^T, single-term ----
        float s_[8][4];
#pragma unroll
        for (int nt = 0; nt < 8; nt++)
#pragma unroll
            for (int q = 0; q < 4; q++) s_[nt][q] = 0.f;

#pragma unroll
        for (int ks = 0; ks < 4; ++ks) {
            const uint32_t kso = (uint32_t)ks * 32;
            uint32_t ah[4];
            ldm_x4(ah, sQ + (uint32_t)(wid * 16) * RPB + kso + lm_off);
            uint32_t bf[4][4];
#pragma unroll
            for (int bp = 0; bp < 4; bp++)
                ldm_x4(bf[bp], sK + (uint32_t)(16 * bp) * RPB + kso + lm_off);
#pragma unroll
            for (int bp = 0; bp < 4; bp++)
#pragma unroll
                for (int half = 0; half < 2; half++)
                    mma_f16(s_[2*bp+half], ah, bf[bp][half], bf[bp][half + 2]);
        }

        // ---- online softmax (log2 domain; Q pre-scaled) ----
        float mlA = -INFINITY, mlB = -INFINITY;
#pragma unroll
        for (int nt = 0; nt < 8; nt++) {
            mlA = fmaxf(mlA, fmaxf(s_[nt][0], s_[nt][1]));
            mlB = fmaxf(mlB, fmaxf(s_[nt][2], s_[nt][3]));
        }
#pragma unroll
        for (int off = 1; off <= 2; off <<= 1) {
            mlA = fmaxf(mlA, __shfl_xor_sync(0xffffffffu, mlA, off));
            mlB = fmaxf(mlB, __shfl_xor_sync(0xffffffffu, mlB, off));
        }
        float mnA = fmaxf(mA, mlA), mnB = fmaxf(mB, mlB);
        float aAl = ex2f(mA - mnA), aBl = ex2f(mB - mnB);
        mA = mnA; mB = mnB;
        float sumA = 0.f, sumB = 0.f;
#pragma unroll
        for (int nt = 0; nt < 8; nt++) {
            s_[nt][0] = ex2f(s_[nt][0] - mA);
            s_[nt][1] = ex2f(s_[nt][1] - mA);
            s_[nt][2] = ex2f(s_[nt][2] - mB);
            s_[nt][3] = ex2f(s_[nt][3] - mB);
            sumA += s_[nt][0] + s_[nt][1];
            sumB += s_[nt][2] + s_[nt][3];
            o_[nt][0] *= aAl; o_[nt][1] *= aAl;
            o_[nt][2] *= aBl; o_[nt][3] *= aBl;
        }
#pragma unroll
        for (int off = 1; off <= 2; off <<= 1) {
            sumA += __shfl_xor_sync(0xffffffffu, sumA, off);
            sumB += __shfl_xor_sync(0xffffffffu, sumB, off);
        }
        lA = lA * aAl + sumA;
        lB = lB * aBl + sumB;

        // ---- O += P @ V, single-term fp16 P ----
#pragma unroll
        for (int t = 0; t < 4; t++) {
            uint32_t pah[4];
#pragma unroll
            for (int i = 0; i < 4; i++) {
                const float* src = (i < 2) ? s_[2 * t] : s_[2 * t + 1];
                pah[i] = pkh2(src[(i & 1) ? 2 : 0], src[(i & 1) ? 3 : 1]);
            }
            uint32_t vf[4][4];
            const uint32_t vrow = (uint32_t)(16 * t + (lane & 7) + ((lane >> 3) & 1) * 8) * RPB
                                + (uint32_t)(lane >> 4) * 16;
#pragma unroll
            for (int db = 0; db < 4; db++)
                ldm_x4_t(vf[db], sV + vrow + (uint32_t)(32 * db));
#pragma unroll
            for (int db = 0; db < 4; db++)
#pragma unroll
                for (int half = 0; half < 2; half++)
                    mma_f16(o_[2*db+half], pah, vf[db][2*half], vf[db][2*half + 1]);
        }
    }

    // ---- epilogue ----
    const int rowA = q0 + 16 * wid + (lane >> 2);
    const int rowB = rowA + 8;
    const float invA = 1.f / lA, invB = 1.f / lB;
#pragma unroll
    for (int nt = 0; nt < 8; nt++) {
        int d0 = 8 * nt + 2 * (lane & 3);
        float2 vA = make_float2(o_[nt][0] * invA, o_[nt][1] * invA);
        float2 vB = make_float2(o_[nt][2] * invB, o_[nt][3] * invB);
        *(float2*)&out[((size_t)b * NN + rowA) * DIM + h * HD + d0] = vA;
        *(float2*)&out[((size_t)b * NN + rowB) * DIM + h * HD + d0] = vB;
    }
}

extern "C" void kernel_launch(void* const* d_in, const int* in_sizes, int n_in,
                              void* d_out, int out_size)
{
    (void)in_sizes; (void)n_in; (void)out_size;
    const float* x  = (const float*)d_in[0];
    const float* wq = (const float*)d_in[1];
    const float* bq = (const float*)d_in[2];
    const float* wk = (const float*)d_in[3];
    const float* bk = (const float*)d_in[4];
    const float* wv = (const float*)d_in[5];
    const float* bv = (const float*)d_in[6];
    float* out = (float*)d_out;

    {
        __half *xh, *xl, *wq16, *wk16, *wv16;
        cudaGetSymbolAddress((void**)&xh, g_xh);
        cudaGetSymbolAddress((void**)&xl, g_xl);
        cudaGetSymbolAddress((void**)&wq16, g_wq16);
        cudaGetSymbolAddress((void**)&wk16, g_wk16);
        cudaGetSymbolAddress((void**)&wv16, g_wv16);
        int n4x = MROWS * DIM / 4;
        split_x<<<(n4x + 255) / 256, 256>>>((const float4*)x, (uint2*)xh, (uint2*)xl, n4x);
        int n4w = DIM * DIM / 4;
        dim3 gw((n4w + 255) / 256, 1, 3);
        cvt_w3<<<gw, 256>>>((const float4*)wq, (const float4*)wk, (const float4*)wv,
                            (uint2*)wq16, (uint2*)wk16, (uint2*)wv16, n4w);
    }

    size_t q_smem = 3 * (size_t)QSTG3;   // 92160 B
    cudaFuncSetAttribute(qkv_mma, cudaFuncAttributeMaxDynamicSharedMemorySize,
                         (int)q_smem);
    dim3 g1(DIM / 128, MROWS / 128, 3);
    qkv_mma<<<g1, 256, q_smem>>>(bq, bk, bv);

    size_t a_smem = (size_t)TILEB + 3 * (size_t)KSTG2;   // 73728 B
    cudaFuncSetAttribute(attn_mma, cudaFuncAttributeMaxDynamicSharedMemorySize,
                         (int)a_smem);
    dim3 g2(NN / 128, NH, BB);
    attn_mma<<<g2, 256, a_smem>>>(out);
}